// round 10
// baseline (speedup 1.0000x reference)
#include <cuda_runtime.h>
#include <cuda.h>
#include <math.h>

#define BB 4
#define T 1024
#define C 1024
#define BT (BB*T)
#define NH 16
#define NKV 4
#define HD 64
#define FFNH 4096
#define CADIM 32
#define VECH 12
#define QKVW 1536

// ---------------- scratch ----------------
__device__ float g_XN[BT*C];
__device__ float g_QKV[BT*QKVW];
__device__ float g_Y[BT*C];
__device__ float g_ATT[BT*C];
__device__ float g_X1[BT*C];
__device__ float g_XM[BT*C];
__device__ float g_HR[(size_t)BT*FFNH];
__device__ float g_H2[(size_t)BT*FFNH];
__device__ float g_GATE[BT*C];
__device__ float g_MLP[BT*C];
__device__ float g_CR[BT*CADIM];
__device__ float g_CA1[BT*CADIM];
__device__ float g_CA2[BT*CADIM];
__device__ float g_VR[BT*CADIM];
__device__ float g_VIT[BT];
__device__ float g_VITF[BT];
// permuted weights
__device__ float g_WQp[1024*C];
__device__ float g_WKp[256*C];
__device__ float g_WVp[256*C];
__device__ float g_WOp[C*C];
__device__ float g_WFIp[(size_t)4096*C];
__device__ float g_WFGp[C*C];
__device__ float g_WFOp[(size_t)C*FFNH];

// ---------------- helpers ----------------
__device__ __forceinline__ unsigned fbits(float x) { return __float_as_uint(x); }
__device__ __forceinline__ float tf32r(float x) {
    unsigned u; asm("cvt.rna.tf32.f32 %0, %1;" : "=r"(u) : "f"(x));
    return __uint_as_float(u);
}
__device__ __forceinline__ int pslot(int k) {
    return (k & ~31) | ((k & 3) << 3) | ((k & 31) >> 2);
}
__device__ __forceinline__ void mma8(float* c, unsigned a0, unsigned a1, unsigned a2, unsigned a3,
                                     unsigned b0, unsigned b1) {
    asm("mma.sync.aligned.m16n8k8.row.col.f32.tf32.tf32.f32 "
        "{%0,%1,%2,%3},{%4,%5,%6,%7},{%8,%9},{%0,%1,%2,%3};"
        : "+f"(c[0]), "+f"(c[1]), "+f"(c[2]), "+f"(c[3])
        : "r"(a0), "r"(a1), "r"(a2), "r"(a3), "r"(b0), "r"(b1));
}
#define MBINIT(addr, cnt) \
    asm volatile("mbarrier.init.shared.b64 [%0], %1;" :: "r"(addr), "r"((uint32_t)(cnt)) : "memory")
#define MBARR(addr) \
    asm volatile("mbarrier.arrive.shared.b64 _, [%0];" :: "r"(addr) : "memory")
#define EXPTX(addr, bytes) \
    asm volatile("mbarrier.arrive.expect_tx.shared.b64 _, [%0], %1;" :: "r"(addr), "r"((uint32_t)(bytes)) : "memory")
#define WAITP(addr, par) do { \
    uint32_t _m = (addr), _p = (par), _d; \
    asm volatile("{\n .reg .pred p;\n mbarrier.try_wait.parity.acquire.cta.shared::cta.b64 p, [%1], %2;\n selp.b32 %0,1,0,p;\n}" \
                 : "=r"(_d) : "r"(_m), "r"(_p) : "memory"); \
    if (!_d) { \
        asm volatile("{\n .reg .pred P1;\nWL_%=:\n mbarrier.try_wait.parity.acquire.cta.shared::cta.b64 P1, [%0], %1, 0x989680;\n @P1 bra.uni WD_%=;\n bra.uni WL_%=;\nWD_%=:\n}" \
                     :: "r"(_m), "r"(_p) : "memory"); \
    } } while (0)
#define TMA2D(saddr, map, cx, cy, mbar) \
    asm volatile("cp.async.bulk.tensor.2d.shared::cta.global.tile.mbarrier::complete_tx::bytes [%0], [%1, {%2, %3}], [%4];" \
                 :: "r"((uint32_t)(saddr)), "l"(map), "r"((int)(cx)), "r"((int)(cy)), "r"((uint32_t)(mbar)) : "memory")

// float4 read from SW128-swizzled 128B-row tile (16B granule)
__device__ __forceinline__ float4 ld4sw(const float* tile, int r, int slot4) {
    int off = (r * 128 + slot4 * 4) ^ ((r & 7) << 4);
    return *(const float4*)((const char*)tile + off);
}

// ---------------- weight permute + round (vectorized) ----------------
__global__ void k_permw4(const float* __restrict__ in, float* __restrict__ out, int n4, int kmask) {
    int i4 = blockIdx.x * 256 + threadIdx.x;
    if (i4 >= n4) return;
    int i = i4 * 4;
    float4 v = *(const float4*)&in[i];
    int k = i & kmask;
    int base = i - k;
    out[base + pslot(k + 0)] = tf32r(v.x);
    out[base + pslot(k + 1)] = tf32r(v.y);
    out[base + pslot(k + 2)] = tf32r(v.z);
    out[base + pslot(k + 3)] = tf32r(v.w);
}

// ---------------- TMA-fed tf32 GEMM, permuted operands, float4 fragments ----------------
// C[M,N] = A[M,K] @ W[N,K]^T (both k-permuted in gmem). EPI: 0 none, 1 relu^2, 2 sigmoid
#define STGB 32768
#define NSTG 3
#define TG_SMEM (1024 + NSTG * STGB + 64)

template<int EPI>
__global__ void __launch_bounds__(256, 2)
k_tgemm(const __grid_constant__ CUtensorMap tmA, const __grid_constant__ CUtensorMap tmB,
        float* __restrict__ Cout, int ldC, int colOff, int K) {
    extern __shared__ float smraw[];
    uint32_t sb0;
    asm("{ .reg .u64 t; cvta.to.shared.u64 t, %1; cvt.u32.u64 %0, t; }" : "=r"(sb0) : "l"(smraw));
    uint32_t sb = (sb0 + 1023) & ~1023u;
    uint32_t MB = sb + NSTG * STGB;     // full[s]@+16s, empty[s]@+16s+8
    const int tid = threadIdx.x, lane = tid & 31, w = tid >> 5;
    const int g = lane >> 2, t4 = lane & 3;
    const int wm = w >> 1, wn = w & 1;
    const int bm = blockIdx.y * 128, bn = blockIdx.x * 128;
    const int nch = K >> 5;
    const float* base = smraw + ((sb - sb0) >> 2);

    if (tid == 0)
        for (int s = 0; s < NSTG; s++) { MBINIT(MB + s * 16, 1); MBINIT(MB + s * 16 + 8, 256); }
    __syncthreads();
    if (tid == 0) {
        #pragma unroll
        for (int s = 0; s < NSTG; s++) {
            EXPTX(MB + s * 16, STGB);
            TMA2D(sb + s * STGB,         &tmA, s * 32, bm, MB + s * 16);
            TMA2D(sb + s * STGB + 16384, &tmB, s * 32, bn, MB + s * 16);
        }
    }

    float acc[2][8][4];
    #pragma unroll
    for (int i = 0; i < 2; i++)
        #pragma unroll
        for (int j = 0; j < 8; j++)
            #pragma unroll
            for (int p = 0; p < 4; p++) acc[i][j][p] = 0.f;

    int st = 0, fph = 0, eph = 0;
    for (int ch = 0; ch < nch; ch++) {
        WAITP(MB + st * 16, (uint32_t)fph);
        const float* Ab = base + st * (STGB >> 2);
        const float* Bb = Ab + 4096;
        #pragma unroll
        for (int kp = 0; kp < 2; kp++) {
            int s4 = t4 * 8 + kp * 4;
            float4 a00 = ld4sw(Ab, wm * 32 + g,      s4);
            float4 a01 = ld4sw(Ab, wm * 32 + 8 + g,  s4);
            float4 a10 = ld4sw(Ab, wm * 32 + 16 + g, s4);
            float4 a11 = ld4sw(Ab, wm * 32 + 24 + g, s4);
            #pragma unroll
            for (int nt = 0; nt < 8; nt++) {
                float4 b4 = ld4sw(Bb, wn * 64 + nt * 8 + g, s4);
                mma8(acc[0][nt], fbits(a00.x), fbits(a01.x), fbits(a00.y), fbits(a01.y),
                     fbits(b4.x), fbits(b4.y));
                mma8(acc[0][nt], fbits(a00.z), fbits(a01.z), fbits(a00.w), fbits(a01.w),
                     fbits(b4.z), fbits(b4.w));
                mma8(acc[1][nt], fbits(a10.x), fbits(a11.x), fbits(a10.y), fbits(a11.y),
                     fbits(b4.x), fbits(b4.y));
                mma8(acc[1][nt], fbits(a10.z), fbits(a11.z), fbits(a10.w), fbits(a11.w),
                     fbits(b4.z), fbits(b4.w));
            }
        }
        MBARR(MB + st * 16 + 8);
        if (tid == 0 && ch + NSTG < nch) {
            WAITP(MB + st * 16 + 8, (uint32_t)eph);
            EXPTX(MB + st * 16, STGB);
            TMA2D(sb + st * STGB,         &tmA, (ch + NSTG) * 32, bm, MB + st * 16);
            TMA2D(sb + st * STGB + 16384, &tmB, (ch + NSTG) * 32, bn, MB + st * 16);
        }
        if (++st == NSTG) { st = 0; fph ^= 1; eph ^= 1; }
    }

    #pragma unroll
    for (int mt = 0; mt < 2; mt++) {
        #pragma unroll
        for (int nt = 0; nt < 8; nt++) {
            int row = bm + wm * 32 + mt * 16 + g;
            int col = bn + wn * 64 + nt * 8 + 2 * t4;
            float v[4];
            #pragma unroll
            for (int p = 0; p < 4; p++) {
                float xv = acc[mt][nt][p];
                if (EPI == 1) { float rr = fmaxf(xv, 0.f); xv = rr * rr; }
                if (EPI == 2) { xv = 1.f / (1.f + __expf(-xv)); }
                v[p] = xv;
            }
            *(float2*)&Cout[(size_t)row * ldC + colOff + col] = make_float2(v[0], v[1]);
            *(float2*)&Cout[(size_t)(row + 8) * ldC + colOff + col] = make_float2(v[2], v[3]);
        }
    }
}

// ---------------- rmsnorm (writes tf32-rounded, k-permuted) ----------------
__global__ void k_rmsnorm(const float* __restrict__ x, float* __restrict__ y) {
    int t = blockIdx.x;
    __shared__ float sx[C];
    __shared__ float red[8];
    const float* xr = x + (size_t)t * C;
    float ss = 0.f;
    for (int i = threadIdx.x; i < C; i += 256) { float v = xr[i]; sx[i] = v; ss += v * v; }
    #pragma unroll
    for (int o = 16; o; o >>= 1) ss += __shfl_xor_sync(0xffffffffu, ss, o);
    if ((threadIdx.x & 31) == 0) red[threadIdx.x >> 5] = ss;
    __syncthreads();
    if (threadIdx.x < 8) {
        float v = red[threadIdx.x];
        #pragma unroll
        for (int o = 4; o; o >>= 1) v += __shfl_xor_sync(0xffu, v, o);
        if (threadIdx.x == 0) red[0] = v;
    }
    __syncthreads();
    float sc = rsqrtf(red[0] / (float)C + 1e-6f);
    float* yr = y + (size_t)t * C;
    for (int i = threadIdx.x; i < C; i += 256) yr[pslot(i)] = tf32r(sx[i] * sc);
}

// ---------------- gate + rope + per-head rmsnorm (XN permuted input) ----------------
__global__ void k_ropegate(float* __restrict__ QKV, const float* __restrict__ XN,
                           const float* __restrict__ ve, const float* __restrict__ cosb,
                           const float* __restrict__ sinb, const float* __restrict__ wveg) {
    int t = blockIdx.x;
    int tt = t & (T - 1);
    __shared__ float sq[NH * HD];
    __shared__ float sr[NH * HD];
    __shared__ float gsm[NKV];
    int tid = threadIdx.x;
    float* Qb = QKV + (size_t)t * QKVW;
    float* Kb = Qb + 1024;
    float* Vb = Qb + 1280;
    if (tid < NKV) {
        float s = 0.f;
        #pragma unroll
        for (int j = 0; j < VECH; j++)
            s += XN[(size_t)t * C + ((j & 3) << 3) + (j >> 2)] * wveg[tid * VECH + j];
        gsm[tid] = 3.f / (1.f + __expf(-s));
    }
    for (int i = tid; i < NH * HD; i += 256) sq[i] = Qb[i];
    __syncthreads();
    for (int i = tid; i < NH * HD; i += 256) {
        int hh = i >> 6, d = i & 63;
        float val;
        if (d < 32) {
            float cv = cosb[tt * 32 + d], sv = sinb[tt * 32 + d];
            val = sq[hh * 64 + d] * cv + sq[hh * 64 + d + 32] * sv;
        } else {
            int d2 = d - 32;
            float cv = cosb[tt * 32 + d2], sv = sinb[tt * 32 + d2];
            val = -sq[hh * 64 + d2] * sv + sq[hh * 64 + d] * cv;
        }
        sr[i] = val;
    }
    __syncthreads();
    int w = tid >> 5, lane = tid & 31;
    for (int hh = w; hh < NH; hh += 8) {
        float v0 = sr[hh * 64 + lane], v1 = sr[hh * 64 + 32 + lane];
        float ss = v0 * v0 + v1 * v1;
        #pragma unroll
        for (int o = 16; o; o >>= 1) ss += __shfl_xor_sync(0xffffffffu, ss, o);
        float sc = rsqrtf(ss / 64.f + 1e-6f) * 1.2f;
        Qb[hh * 64 + lane] = v0 * sc;
        Qb[hh * 64 + 32 + lane] = v1 * sc;
    }
    __syncthreads();
    for (int i = tid; i < NKV * HD; i += 256) sq[i] = Kb[i];
    __syncthreads();
    for (int i = tid; i < NKV * HD; i += 256) {
        int hh = i >> 6, d = i & 63;
        float val;
        if (d < 32) {
            float cv = cosb[tt * 32 + d], sv = sinb[tt * 32 + d];
            val = sq[hh * 64 + d] * cv + sq[hh * 64 + d + 32] * sv;
        } else {
            int d2 = d - 32;
            float cv = cosb[tt * 32 + d2], sv = sinb[tt * 32 + d2];
            val = -sq[hh * 64 + d2] * sv + sq[hh * 64 + d] * cv;
        }
        sr[i] = val;
    }
    __syncthreads();
    if (w < NKV) {
        int hh = w;
        float v0 = sr[hh * 64 + lane], v1 = sr[hh * 64 + 32 + lane];
        float ss = v0 * v0 + v1 * v1;
        #pragma unroll
        for (int o = 16; o; o >>= 1) ss += __shfl_xor_sync(0xffffffffu, ss, o);
        float sc = rsqrtf(ss / 64.f + 1e-6f) * 1.2f;
        Kb[hh * 64 + lane] = v0 * sc;
        Kb[hh * 64 + 32 + lane] = v1 * sc;
    }
    {
        Vb[tid] = Vb[tid] + gsm[tid >> 6] * ve[(size_t)t * (NKV * HD) + tid];
    }
}

// ---------------- flash attention (R6 version; Y written permuted) ----------------
__global__ void __launch_bounds__(256) k_flash(const float* __restrict__ QKV, const float* __restrict__ prev,
                        const float* __restrict__ rw, const float* __restrict__ alphap,
                        float* __restrict__ Y) {
    extern __shared__ float smf[];
    float* Qs = smf;
    float* KS = Qs + 64 * 68;
    float* Vt = KS + 64 * 68;
    float* Ps = Vt + 64 * 68;
    float* mrow = Ps + 66 * 66;
    float* lrow = mrow + 64;
    float* crow = lrow + 64;
    int tid = threadIdx.x, lane = tid & 31, w = tid >> 5;
    int g = lane >> 2, t4 = lane & 3;
    int wm = w >> 1, wn = w & 1;
    int qt = gridDim.x - 1 - blockIdx.x;
    int h = blockIdx.y, b = blockIdx.z;
    int q0 = qt * 64, hk = h >> 2;
    float alpha = alphap[0];
    float w9[9];
    #pragma unroll
    for (int i = 0; i < 9; i++) w9[i] = rw[h * 9 + i];

    for (int i = tid; i < 1024; i += 256) {
        int rr = i >> 4, d4 = (i & 15) << 2;
        float4 qv = *(const float4*)&QKV[((size_t)(b * T) + q0 + rr) * QKVW + h * 64 + d4];
        Qs[rr * 68 + pslot(d4 + 0)] = qv.x;
        Qs[rr * 68 + pslot(d4 + 1)] = qv.y;
        Qs[rr * 68 + pslot(d4 + 2)] = qv.z;
        Qs[rr * 68 + pslot(d4 + 3)] = qv.w;
    }
    if (tid < 64) { mrow[tid] = -INFINITY; lrow[tid] = 0.f; }
    float o[4][4];
    #pragma unroll
    for (int i = 0; i < 4; i++)
        #pragma unroll
        for (int j = 0; j < 4; j++) o[i][j] = 0.f;

    for (int kt = 0; kt <= qt; kt++) {
        int k0 = kt * 64;
        __syncthreads();
        for (int i = tid; i < 1024; i += 256) {
            int rr = i >> 4, d4 = (i & 15) << 2;
            const float* basep = &QKV[((size_t)(b * T) + k0 + rr) * QKVW];
            float4 kv = *(const float4*)&basep[1024 + hk * 64 + d4];
            KS[rr * 68 + pslot(d4 + 0)] = kv.x;
            KS[rr * 68 + pslot(d4 + 1)] = kv.y;
            KS[rr * 68 + pslot(d4 + 2)] = kv.z;
            KS[rr * 68 + pslot(d4 + 3)] = kv.w;
            float4 vv = *(const float4*)&basep[1280 + hk * 64 + d4];
            int pr = pslot(rr);
            Vt[(d4 + 0) * 68 + pr] = vv.x;
            Vt[(d4 + 1) * 68 + pr] = vv.y;
            Vt[(d4 + 2) * 68 + pr] = vv.z;
            Vt[(d4 + 3) * 68 + pr] = vv.w;
        }
        for (int idx = tid; idx < 66 * 66; idx += 256) {
            int li = idx / 66, lj = idx - li * 66;
            int gi = q0 - 1 + li, gj = k0 - 1 + lj;
            float v = 0.f;
            if (gi >= 0 && gi < T && gj >= 0 && gj < T)
                v = prev[(((size_t)(b * NH) + h) * T + gi) * T + gj];
            Ps[idx] = v;
        }
        __syncthreads();
        float sacc[4][4];
        #pragma unroll
        for (int i = 0; i < 4; i++)
            #pragma unroll
            for (int j = 0; j < 4; j++) sacc[i][j] = 0.f;
        #pragma unroll
        for (int kp = 0; kp < 4; kp++) {
            int koff = (kp >> 1) * 32 + t4 * 8 + (kp & 1) * 4;
            float4 af0 = *(float4*)&Qs[(wm * 16 + g) * 68 + koff];
            float4 af1 = *(float4*)&Qs[(wm * 16 + 8 + g) * 68 + koff];
            float4 bf[4];
            #pragma unroll
            for (int nt = 0; nt < 4; nt++)
                bf[nt] = *(float4*)&KS[(wn * 32 + nt * 8 + g) * 68 + koff];
            #pragma unroll
            for (int kk = 0; kk < 2; kk++) {
                unsigned a0 = fbits(kk ? af0.z : af0.x), a2 = fbits(kk ? af0.w : af0.y);
                unsigned a1 = fbits(kk ? af1.z : af1.x), a3 = fbits(kk ? af1.w : af1.y);
                #pragma unroll
                for (int nt = 0; nt < 4; nt++) {
                    unsigned b0 = fbits(kk ? bf[nt].z : bf[nt].x);
                    unsigned b1 = fbits(kk ? bf[nt].w : bf[nt].y);
                    mma8(sacc[nt], a0, a1, a2, a3, b0, b1);
                }
            }
        }
        __syncthreads();
        #pragma unroll
        for (int nt = 0; nt < 4; nt++) {
            #pragma unroll
            for (int rg = 0; rg < 2; rg++) {
                int ri = wm * 16 + g + rg * 8;
                int cj = wn * 32 + nt * 8 + 2 * t4;
                float p[3][4];
                #pragma unroll
                for (int a = 0; a < 3; a++) {
                    float2 x0 = *(float2*)&Ps[(ri + a) * 66 + cj];
                    float2 x1 = *(float2*)&Ps[(ri + a) * 66 + cj + 2];
                    p[a][0] = x0.x; p[a][1] = x0.y; p[a][2] = x1.x; p[a][3] = x1.y;
                }
                float cv0 = 0.f, cv1 = 0.f;
                #pragma unroll
                for (int a = 0; a < 3; a++)
                    #pragma unroll
                    for (int bb = 0; bb < 3; bb++) {
                        cv0 = fmaf(w9[a * 3 + bb], p[a][bb], cv0);
                        cv1 = fmaf(w9[a * 3 + bb], p[a][bb + 1], cv1);
                    }
                float v0 = sacc[nt][rg * 2 + 0] * 0.125f + alpha * cv0;
                float v1 = sacc[nt][rg * 2 + 1] * 0.125f + alpha * cv1;
                if (k0 + cj > q0 + ri) v0 = -INFINITY;
                if (k0 + cj + 1 > q0 + ri) v1 = -INFINITY;
                KS[ri * 68 + pslot(cj)] = v0;
                KS[ri * 68 + pslot(cj + 1)] = v1;
            }
        }
        __syncthreads();
        {
            int row = tid >> 2, part = tid & 3;
            float* srow = KS + row * 68 + part * 16;
            float4 s0 = *(float4*)&srow[0], s1 = *(float4*)&srow[4];
            float4 s2 = *(float4*)&srow[8], s3 = *(float4*)&srow[12];
            float rm = fmaxf(fmaxf(fmaxf(s0.x, s0.y), fmaxf(s0.z, s0.w)),
                             fmaxf(fmaxf(s1.x, s1.y), fmaxf(s1.z, s1.w)));
            rm = fmaxf(rm, fmaxf(fmaxf(fmaxf(s2.x, s2.y), fmaxf(s2.z, s2.w)),
                                 fmaxf(fmaxf(s3.x, s3.y), fmaxf(s3.z, s3.w))));
            rm = fmaxf(rm, __shfl_xor_sync(0xffffffffu, rm, 1));
            rm = fmaxf(rm, __shfl_xor_sync(0xffffffffu, rm, 2));
            float mo = mrow[row];
            float nm = fmaxf(mo, rm);
            float sum = 0.f;
            #define EXA(v) v.x = __expf(v.x - nm); v.y = __expf(v.y - nm); \
                           v.z = __expf(v.z - nm); v.w = __expf(v.w - nm); \
                           sum += v.x + v.y + v.z + v.w;
            EXA(s0) EXA(s1) EXA(s2) EXA(s3)
            #undef EXA
            *(float4*)&srow[0] = s0; *(float4*)&srow[4] = s1;
            *(float4*)&srow[8] = s2; *(float4*)&srow[12] = s3;
            sum += __shfl_xor_sync(0xffffffffu, sum, 1);
            sum += __shfl_xor_sync(0xffffffffu, sum, 2);
            if (part == 0) {
                float corr = __expf(mo - nm);
                mrow[row] = nm;
                lrow[row] = lrow[row] * corr + sum;
                crow[row] = corr;
            }
        }
        __syncthreads();
        float c0 = crow[wm * 16 + g], c1 = crow[wm * 16 + 8 + g];
        #pragma unroll
        for (int nt = 0; nt < 4; nt++) {
            o[nt][0] *= c0; o[nt][1] *= c0; o[nt][2] *= c1; o[nt][3] *= c1;
        }
        #pragma unroll
        for (int kp = 0; kp < 4; kp++) {
            int koff = (kp >> 1) * 32 + t4 * 8 + (kp & 1) * 4;
            float4 af0 = *(float4*)&KS[(wm * 16 + g) * 68 + koff];
            float4 af1 = *(float4*)&KS[(wm * 16 + 8 + g) * 68 + koff];
            float4 bf[4];
            #pragma unroll
            for (int nt = 0; nt < 4; nt++)
                bf[nt] = *(float4*)&Vt[(wn * 32 + nt * 8 + g) * 68 + koff];
            #pragma unroll
            for (int kk = 0; kk < 2; kk++) {
                unsigned a0 = fbits(kk ? af0.z : af0.x), a2 = fbits(kk ? af0.w : af0.y);
                unsigned a1 = fbits(kk ? af1.z : af1.x), a3 = fbits(kk ? af1.w : af1.y);
                #pragma unroll
                for (int nt = 0; nt < 4; nt++) {
                    unsigned b0 = fbits(kk ? bf[nt].z : bf[nt].x);
                    unsigned b1 = fbits(kk ? bf[nt].w : bf[nt].y);
                    mma8(o[nt], a0, a1, a2, a3, b0, b1);
                }
            }
        }
    }
    {
        float inv0 = 1.f / lrow[wm * 16 + g];
        float inv1 = 1.f / lrow[wm * 16 + 8 + g];
        int r0 = q0 + wm * 16 + g;
        #pragma unroll
        for (int nt = 0; nt < 4; nt++) {
            int cj = wn * 32 + nt * 8 + 2 * t4;
            int c0i = h * 64 + cj;
            Y[((size_t)(b * T) + r0) * C + pslot(c0i)] = o[nt][0] * inv0;
            Y[((size_t)(b * T) + r0) * C + pslot(c0i + 1)] = o[nt][1] * inv0;
            Y[((size_t)(b * T) + r0 + 8) * C + pslot(c0i)] = o[nt][2] * inv1;
            Y[((size_t)(b * T) + r0 + 8) * C + pslot(c0i + 1)] = o[nt][3] * inv1;
        }
    }
}

// ---------------- small kernels ----------------
__global__ void k_dot32(const float* __restrict__ X, const float* __restrict__ W,
                        float* __restrict__ OUT) {
    __shared__ float sx[8 * C];
    int t0 = blockIdx.x * 8;
    for (int i = threadIdx.x; i < 8 * C; i += 256) sx[i] = X[(size_t)t0 * C + i];
    __syncthreads();
    int tok = threadIdx.x >> 5, oo = threadIdx.x & 31;
    const float4* wr = (const float4*)(W + (size_t)oo * C);
    const float4* xr = (const float4*)(sx + tok * C);
    float s = 0.f;
    #pragma unroll 4
    for (int k = 0; k < C / 4; k++) {
        float4 a = xr[k], b = wr[k];
        s += a.x * b.x + a.y * b.y + a.z * b.z + a.w * b.w;
    }
    OUT[(size_t)(t0 + tok) * CADIM + oo] = s;
}

__global__ void k_caconv(const float* __restrict__ R, const float* __restrict__ cw,
                         float* __restrict__ OUT) {
    int b = blockIdx.y, t0 = blockIdx.x * 128;
    __shared__ float s[130 * 32];
    __shared__ float w[32 * 3];
    for (int i = threadIdx.x; i < 96; i += 256) w[i] = cw[i];
    for (int i = threadIdx.x; i < 130 * 32; i += 256) {
        int r = i >> 5, c = i & 31;
        int t = t0 - 1 + r;
        s[i] = (t >= 0 && t < T) ? R[((size_t)(b * T) + t) * CADIM + c] : 0.f;
    }
    __syncthreads();
    for (int i = threadIdx.x; i < 128 * 32; i += 256) {
        int r = i >> 5, c = i & 31;
        float h0 = s[(r + 1) * 32 + c];
        float cv = w[c * 3 + 0] * s[r * 32 + c] + w[c * 3 + 1] * h0 + w[c * 3 + 2] * s[(r + 2) * 32 + c];
        float v = h0 + 0.1f * cv;
        v = 0.5f * v * (1.f + erff(v * 0.70710678118f));
        OUT[((size_t)(b * T) + t0 + r) * CADIM + c] = v;
    }
}

__global__ void k_x1(const float* __restrict__ x, const float* __restrict__ attn,
                     const float* __restrict__ cah, const float* __restrict__ capo,
                     float* __restrict__ X1) {
    int tg = blockIdx.x;
    __shared__ float h[16 * 32];
    __shared__ float po[256 * 33];
    int tid = threadIdx.x;
    for (int i = tid; i < 16 * 32; i += 256) h[i] = cah[(size_t)tg * 16 * 32 + i];
    for (int cc = 0; cc < 4; cc++) {
        int c0 = cc * 256;
        __syncthreads();
        for (int i = tid; i < 256 * 32; i += 256) po[(i >> 5) * 33 + (i & 31)] = capo[(size_t)c0 * 32 + i];
        __syncthreads();
        float wv[32];
        #pragma unroll
        for (int j = 0; j < 32; j++) wv[j] = po[tid * 33 + j];
        int c = c0 + tid;
        for (int tok = 0; tok < 16; tok++) {
            float ca = 0.f;
            #pragma unroll
            for (int j = 0; j < 32; j++) ca = fmaf(wv[j], h[tok * 32 + j], ca);
            size_t idx = ((size_t)tg * 16 + tok) * C + c;
            X1[idx] = x[idx] + attn[idx] * (1.f + 0.1f * tanhf(ca));
        }
    }
}

// FFN depthwise conv, 4 fused iterations; writes permuted + rounded
__global__ void k_ffnconv(const float* __restrict__ Hin, const float* __restrict__ cw,
                          float* __restrict__ Hout) {
    int c0 = blockIdx.x * 32, t0 = blockIdx.y * 64, b = blockIdx.z;
    __shared__ float bufA[72 * 32];
    __shared__ float bufB[72 * 32];
    __shared__ float w[32 * 3];
    int tid = threadIdx.x;
    for (int i = tid; i < 96; i += 256) w[i] = cw[(size_t)c0 * 3 + i];
    for (int i = tid; i < 72 * 32; i += 256) {
        int r = i >> 5, c = i & 31;
        int t = t0 - 4 + r;
        bufA[i] = (t >= 0 && t < T) ? Hin[((size_t)(b * T) + t) * FFNH + c0 + c] : 0.f;
    }
    float* A = bufA;
    float* Bf = bufB;
    for (int it = 0; it < 4; it++) {
        __syncthreads();
        for (int i = tid; i < 72 * 32; i += 256) {
            int r = i >> 5, c = i & 31;
            int t = t0 - 4 + r;
            float v = 0.f;
            if (t >= 0 && t < T) {
                float am = (r > 0) ? A[(r - 1) * 32 + c] : 0.f;
                float a0 = A[i];
                float ap = (r < 71) ? A[(r + 1) * 32 + c] : 0.f;
                v = a0 + 0.1f * (w[c * 3] * am + w[c * 3 + 1] * a0 + w[c * 3 + 2] * ap);
            }
            Bf[i] = v;
        }
        float* tmp = A; A = Bf; Bf = tmp;
    }
    __syncthreads();
    for (int i = tid; i < 64 * 32; i += 256) {
        int r = i >> 5, c = i & 31;
        int s = c0 + ((c & 3) << 3) + (c >> 2);
        Hout[((size_t)(b * T) + t0 + r) * FFNH + s] = tf32r(A[(r + 4) * 32 + c]);
    }
}

__global__ void k_vitpost(const float* __restrict__ VR, const float* __restrict__ w2,
                          float* __restrict__ VIT) {
    int t = blockIdx.x * 256 + threadIdx.x;
    float s = 0.f;
    #pragma unroll
    for (int j = 0; j < 32; j++) {
        float v = VR[(size_t)t * 32 + j];
        v = 0.5f * v * (1.f + erff(v * 0.70710678118f));
        s += v * w2[j];
    }
    VIT[t] = 1.f / (1.f + __expf(-s));
}

__global__ void k_vsmooth(const float* __restrict__ VIT, float* __restrict__ VITF) {
    int b = blockIdx.x;
    for (int t = threadIdx.x; t < T; t += 256) {
        float v = VIT[b * T + t];
        float s = 0.f;
        #pragma unroll
        for (int d = -2; d <= 2; d++) {
            int tt = t + d;
            if (tt >= 0 && tt < T) s += VIT[b * T + tt];
        }
        s *= 0.2f;
        float f = 0.7f * v + 0.3f * s;
        VITF[b * T + t] = (f > 0.3f) ? f : 0.1f * f;
    }
}

__global__ void k_final(const float* __restrict__ x1, const float* __restrict__ mlp,
                        const float* __restrict__ gate, const float* __restrict__ cah,
                        const float* __restrict__ capo, const float* __restrict__ vitf,
                        float* __restrict__ out) {
    int tg = blockIdx.x;
    __shared__ float h[16 * 32];
    __shared__ float po[256 * 33];
    __shared__ float sv[16];
    int tid = threadIdx.x;
    for (int i = tid; i < 16 * 32; i += 256) h[i] = cah[(size_t)tg * 16 * 32 + i];
    if (tid < 16) sv[tid] = vitf[tg * 16 + tid];
    for (int cc = 0; cc < 4; cc++) {
        int c0 = cc * 256;
        __syncthreads();
        for (int i = tid; i < 256 * 32; i += 256) po[(i >> 5) * 33 + (i & 31)] = capo[(size_t)c0 * 32 + i];
        __syncthreads();
        float wv[32];
        #pragma unroll
        for (int j = 0; j < 32; j++) wv[j] = po[tid * 33 + j];
        int c = c0 + tid;
        for (int tok = 0; tok < 16; tok++) {
            float ca = 0.f;
            #pragma unroll
            for (int j = 0; j < 32; j++) ca = fmaf(wv[j], h[tok * 32 + j], ca);
            size_t idx = ((size_t)tg * 16 + tok) * C + c;
            float m = mlp[idx] * gate[idx] * (1.f + 0.1f * tanhf(ca)) * sv[tok];
            out[idx] = x1[idx] + m;
        }
    }
}

// ---------------- host ----------------
typedef CUresult (*PFN_tmenc)(CUtensorMap*, CUtensorMapDataType, cuuint32_t, void*,
                              const cuuint64_t*, const cuuint64_t*, const cuuint32_t*,
                              const cuuint32_t*, CUtensorMapInterleave, CUtensorMapSwizzle,
                              CUtensorMapL2promotion, CUtensorMapFloatOOBfill);
static PFN_tmenc tmenc() {
    static PFN_tmenc fp = nullptr;
    if (!fp) {
        void* p = nullptr;
        cudaDriverEntryPointQueryResult qr;
        cudaGetDriverEntryPoint("cuTensorMapEncodeTiled", &p, cudaEnableDefault, &qr);
        fp = (PFN_tmenc)p;
    }
    return fp;
}
static void mk_tmap(CUtensorMap* m, const void* ptr, int M, int K) {
    cuuint64_t dims[2] = {(cuuint64_t)K, (cuuint64_t)M};
    cuuint64_t strides[1] = {(cuuint64_t)K * 4};
    cuuint32_t box[2] = {32, 128};
    cuuint32_t es[2] = {1, 1};
    tmenc()(m, CU_TENSOR_MAP_DATA_TYPE_FLOAT32, 2, (void*)ptr, dims, strides, box, es,
            CU_TENSOR_MAP_INTERLEAVE_NONE, CU_TENSOR_MAP_SWIZZLE_128B,
            CU_TENSOR_MAP_L2_PROMOTION_L2_128B, CU_TENSOR_MAP_FLOAT_OOB_FILL_NONE);
}

extern "C" void kernel_launch(void* const* d_in, const int* in_sizes, int n_in,
                              void* d_out, int out_size) {
    const float* x        = (const float*)d_in[0];
    const float* ve       = (const float*)d_in[1];
    const float* cosb     = (const float*)d_in[2];
    const float* sinb     = (const float*)d_in[3];
    const float* prev     = (const float*)d_in[4];
    const float* w_q      = (const float*)d_in[5];
    const float* w_k      = (const float*)d_in[6];
    const float* w_v      = (const float*)d_in[7];
    const float* w_o      = (const float*)d_in[8];
    const float* w_veg    = (const float*)d_in[9];
    const float* refine_w = (const float*)d_in[10];
    const float* alpha    = (const float*)d_in[11];
    const float* ca_pi    = (const float*)d_in[12];
    const float* ca_cw    = (const float*)d_in[13];
    const float* ca_po    = (const float*)d_in[14];
    const float* ffn_in   = (const float*)d_in[15];
    const float* ffn_cw   = (const float*)d_in[16];
    const float* ffn_out  = (const float*)d_in[17];
    const float* ffn_gate = (const float*)d_in[18];
    const float* vit_w1   = (const float*)d_in[19];
    const float* vit_w2   = (const float*)d_in[20];
    float* out = (float*)d_out;

    float *XN, *QKV, *Yp, *ATT, *X1, *XM, *HR, *H2, *GATE, *MLP, *CR, *CA1, *CA2, *VR, *VIT, *VITF;
    float *WQp, *WKp, *WVp, *WOp, *WFIp, *WFGp, *WFOp;
    cudaGetSymbolAddress((void**)&XN, g_XN);
    cudaGetSymbolAddress((void**)&QKV, g_QKV);
    cudaGetSymbolAddress((void**)&Yp, g_Y);
    cudaGetSymbolAddress((void**)&ATT, g_ATT);
    cudaGetSymbolAddress((void**)&X1, g_X1);
    cudaGetSymbolAddress((void**)&XM, g_XM);
    cudaGetSymbolAddress((void**)&HR, g_HR);
    cudaGetSymbolAddress((void**)&H2, g_H2);
    cudaGetSymbolAddress((void**)&GATE, g_GATE);
    cudaGetSymbolAddress((void**)&MLP, g_MLP);
    cudaGetSymbolAddress((void**)&CR, g_CR);
    cudaGetSymbolAddress((void**)&CA1, g_CA1);
    cudaGetSymbolAddress((void**)&CA2, g_CA2);
    cudaGetSymbolAddress((void**)&VR, g_VR);
    cudaGetSymbolAddress((void**)&VIT, g_VIT);
    cudaGetSymbolAddress((void**)&VITF, g_VITF);
    cudaGetSymbolAddress((void**)&WQp, g_WQp);
    cudaGetSymbolAddress((void**)&WKp, g_WKp);
    cudaGetSymbolAddress((void**)&WVp, g_WVp);
    cudaGetSymbolAddress((void**)&WOp, g_WOp);
    cudaGetSymbolAddress((void**)&WFIp, g_WFIp);
    cudaGetSymbolAddress((void**)&WFGp, g_WFGp);
    cudaGetSymbolAddress((void**)&WFOp, g_WFOp);

    static CUtensorMap tXN, tWQ, tWK, tWV, tY, tWO, tXM, tFI, tFG, tH2, tFO;
    mk_tmap(&tXN, XN, BT, C);
    mk_tmap(&tWQ, WQp, 1024, C);
    mk_tmap(&tWK, WKp, 256, C);
    mk_tmap(&tWV, WVp, 256, C);
    mk_tmap(&tY, Yp, BT, C);
    mk_tmap(&tWO, WOp, 1024, C);
    mk_tmap(&tXM, XM, BT, C);
    mk_tmap(&tFI, WFIp, 4096, C);
    mk_tmap(&tFG, WFGp, 1024, C);
    mk_tmap(&tH2, H2, BT, FFNH);
    mk_tmap(&tFO, WFOp, 1024, FFNH);

    cudaFuncSetAttribute(k_tgemm<0>, cudaFuncAttributeMaxDynamicSharedMemorySize, TG_SMEM);
    cudaFuncSetAttribute(k_tgemm<1>, cudaFuncAttributeMaxDynamicSharedMemorySize, TG_SMEM);
    cudaFuncSetAttribute(k_tgemm<2>, cudaFuncAttributeMaxDynamicSharedMemorySize, TG_SMEM);
    const int smemf = (3 * 64 * 68 + 66 * 66 + 3 * 64) * (int)sizeof(float);
    cudaFuncSetAttribute(k_flash, cudaFuncAttributeMaxDynamicSharedMemorySize, smemf);

    // permute + tf32-round weights into scratch
    k_permw4<<<(1024 * 256 + 255) / 256, 256>>>(w_q, WQp, 1024 * 256, 1023);
    k_permw4<<<(256 * 256 + 255) / 256, 256>>>(w_k, WKp, 256 * 256, 1023);
    k_permw4<<<(256 * 256 + 255) / 256, 256>>>(w_v, WVp, 256 * 256, 1023);
    k_permw4<<<(1024 * 256 + 255) / 256, 256>>>(w_o, WOp, 1024 * 256, 1023);
    k_permw4<<<(4096 * 256 + 255) / 256, 256>>>(ffn_in, WFIp, 4096 * 256, 1023);
    k_permw4<<<(1024 * 256 + 255) / 256, 256>>>(ffn_gate, WFGp, 1024 * 256, 1023);
    k_permw4<<<(1024 * 1024 + 255) / 256, 256>>>(ffn_out, WFOp, 1024 * 1024, 4095);

    k_rmsnorm<<<BT, 256>>>(x, XN);
    k_tgemm<0><<<dim3(8, 32), 256, TG_SMEM>>>(tXN, tWQ, QKV, QKVW, 0, C);
    k_tgemm<0><<<dim3(2, 32), 256, TG_SMEM>>>(tXN, tWK, QKV, QKVW, 1024, C);
    k_tgemm<0><<<dim3(2, 32), 256, TG_SMEM>>>(tXN, tWV, QKV, QKVW, 1280, C);
    k_ropegate<<<BT, 256>>>(QKV, XN, ve, cosb, sinb, w_veg);

    k_flash<<<dim3(T / 64, NH, BB), 256, smemf>>>(QKV, prev, refine_w, alpha, Yp);

    k_tgemm<0><<<dim3(8, 32), 256, TG_SMEM>>>(tY, tWO, ATT, C, 0, C);

    k_dot32<<<BT / 8, 256>>>(x, ca_pi, CR);
    k_caconv<<<dim3(T / 128, BB), 256>>>(CR, ca_cw, CA1);
    k_x1<<<BT / 16, 256>>>(x, ATT, CA1, ca_po, X1);

    k_rmsnorm<<<BT, 256>>>(X1, XM);
    k_tgemm<1><<<dim3(32, 32), 256, TG_SMEM>>>(tXM, tFI, HR, FFNH, 0, C);
    k_tgemm<2><<<dim3(8, 32), 256, TG_SMEM>>>(tXM, tFG, GATE, C, 0, C);
    k_ffnconv<<<dim3(FFNH / 32, T / 64, BB), 256>>>(HR, ffn_cw, H2);
    k_tgemm<0><<<dim3(8, 32), 256, TG_SMEM>>>(tH2, tFO, MLP, C, 0, FFNH);

    k_dot32<<<BT / 8, 256>>>(X1, ca_pi, CR);
    k_caconv<<<dim3(T / 128, BB), 256>>>(CR, ca_cw, CA2);
    k_dot32<<<BT / 8, 256>>>(X1, vit_w1, VR);
    k_vitpost<<<BT / 256, 256>>>(VR, vit_w2, VIT);
    k_vsmooth<<<BB, 256>>>(VIT, VITF);

    k_final<<<BT / 16, 256>>>(X1, MLP, GATE, CA2, ca_po, VITF, out);
}

// round 11
// speedup vs baseline: 1.0814x; 1.0814x over previous
#include <cuda_runtime.h>
#include <cuda.h>
#include <math.h>

#define BB 4
#define T 1024
#define C 1024
#define BT (BB*T)
#define NH 16
#define NKV 4
#define HD 64
#define FFNH 4096
#define CADIM 32
#define VECH 12
#define QKVW 1536
#define FW 5120

// ---------------- scratch ----------------
__device__ float g_XN[BT*C];
__device__ float g_QKV[BT*QKVW];
__device__ float g_Y[BT*C];
__device__ float g_ATT[BT*C];
__device__ float g_X1[BT*C];
__device__ float g_XM[BT*C];
__device__ float g_HG[(size_t)BT*FW];
__device__ float g_H2[(size_t)BT*FFNH];
__device__ float g_MLP[BT*C];
__device__ float g_CR1[BT*CADIM];
__device__ float g_CA1[BT*CADIM];
__device__ float g_CR2[BT*CADIM];
__device__ float g_CA2[BT*CADIM];
__device__ float g_VR[BT*CADIM];
__device__ float g_VIT[BT];
__device__ float g_VITF[BT];
// permuted weights (fused)
__device__ float g_WQKVp[(size_t)QKVW*C];
__device__ float g_WOp[C*C];
__device__ float g_WFp[(size_t)FW*C];
__device__ float g_WFOp[(size_t)C*FFNH];

// ---------------- helpers ----------------
__device__ __forceinline__ unsigned fbits(float x) { return __float_as_uint(x); }
__device__ __forceinline__ float tf32r(float x) {
    unsigned u; asm("cvt.rna.tf32.f32 %0, %1;" : "=r"(u) : "f"(x));
    return __uint_as_float(u);
}
__device__ __forceinline__ int pslot(int k) {
    return (k & ~31) | ((k & 3) << 3) | ((k & 31) >> 2);
}
__device__ __forceinline__ void mma8(float* c, unsigned a0, unsigned a1, unsigned a2, unsigned a3,
                                     unsigned b0, unsigned b1) {
    asm("mma.sync.aligned.m16n8k8.row.col.f32.tf32.tf32.f32 "
        "{%0,%1,%2,%3},{%4,%5,%6,%7},{%8,%9},{%0,%1,%2,%3};"
        : "+f"(c[0]), "+f"(c[1]), "+f"(c[2]), "+f"(c[3])
        : "r"(a0), "r"(a1), "r"(a2), "r"(a3), "r"(b0), "r"(b1));
}
#define MBINIT(addr, cnt) \
    asm volatile("mbarrier.init.shared.b64 [%0], %1;" :: "r"(addr), "r"((uint32_t)(cnt)) : "memory")
#define MBARR(addr) \
    asm volatile("mbarrier.arrive.shared.b64 _, [%0];" :: "r"(addr) : "memory")
#define EXPTX(addr, bytes) \
    asm volatile("mbarrier.arrive.expect_tx.shared.b64 _, [%0], %1;" :: "r"(addr), "r"((uint32_t)(bytes)) : "memory")
#define WAITP(addr, par) do { \
    uint32_t _m = (addr), _p = (par), _d; \
    asm volatile("{\n .reg .pred p;\n mbarrier.try_wait.parity.acquire.cta.shared::cta.b64 p, [%1], %2;\n selp.b32 %0,1,0,p;\n}" \
                 : "=r"(_d) : "r"(_m), "r"(_p) : "memory"); \
    if (!_d) { \
        asm volatile("{\n .reg .pred P1;\nWL_%=:\n mbarrier.try_wait.parity.acquire.cta.shared::cta.b64 P1, [%0], %1, 0x989680;\n @P1 bra.uni WD_%=;\n bra.uni WL_%=;\nWD_%=:\n}" \
                     :: "r"(_m), "r"(_p) : "memory"); \
    } } while (0)
#define TMA2D(saddr, map, cx, cy, mbar) \
    asm volatile("cp.async.bulk.tensor.2d.shared::cta.global.tile.mbarrier::complete_tx::bytes [%0], [%1, {%2, %3}], [%4];" \
                 :: "r"((uint32_t)(saddr)), "l"(map), "r"((int)(cx)), "r"((int)(cy)), "r"((uint32_t)(mbar)) : "memory")

__device__ __forceinline__ float4 ld4sw(const float* tile, int r, int slot4) {
    int off = (r * 128 + slot4 * 4) ^ ((r & 7) << 4);
    return *(const float4*)((const char*)tile + off);
}

// ---------------- weight permute + round ----------------
__global__ void k_permw4(const float* __restrict__ in, float* __restrict__ out, int n4, int kmask) {
    int i4 = blockIdx.x * 256 + threadIdx.x;
    if (i4 >= n4) return;
    int i = i4 * 4;
    float4 v = *(const float4*)&in[i];
    int k = i & kmask;
    int base = i - k;
    out[base + pslot(k + 0)] = tf32r(v.x);
    out[base + pslot(k + 1)] = tf32r(v.y);
    out[base + pslot(k + 2)] = tf32r(v.z);
    out[base + pslot(k + 3)] = tf32r(v.w);
}

// ---------------- TMA-fed tf32 GEMM (permuted operands) ----------------
// EPI: 0 none, 3 = (global col<4096 ? relu^2 : sigmoid)
#define STGB 32768
#define NSTG 3
#define TG_SMEM (1024 + NSTG * STGB + 64)

template<int EPI>
__global__ void __launch_bounds__(256, 2)
k_tgemm(const __grid_constant__ CUtensorMap tmA, const __grid_constant__ CUtensorMap tmB,
        float* __restrict__ Cout, int ldC, int colOff, int K) {
    extern __shared__ float smraw[];
    uint32_t sb0;
    asm("{ .reg .u64 t; cvta.to.shared.u64 t, %1; cvt.u32.u64 %0, t; }" : "=r"(sb0) : "l"(smraw));
    uint32_t sb = (sb0 + 1023) & ~1023u;
    uint32_t MB = sb + NSTG * STGB;
    const int tid = threadIdx.x, lane = tid & 31, w = tid >> 5;
    const int g = lane >> 2, t4 = lane & 3;
    const int wm = w >> 1, wn = w & 1;
    const int bm = blockIdx.y * 128, bn = blockIdx.x * 128;
    const int nch = K >> 5;
    const float* base = smraw + ((sb - sb0) >> 2);

    if (tid == 0)
        for (int s = 0; s < NSTG; s++) { MBINIT(MB + s * 16, 1); MBINIT(MB + s * 16 + 8, 256); }
    __syncthreads();
    if (tid == 0) {
        #pragma unroll
        for (int s = 0; s < NSTG; s++) {
            EXPTX(MB + s * 16, STGB);
            TMA2D(sb + s * STGB,         &tmA, s * 32, bm, MB + s * 16);
            TMA2D(sb + s * STGB + 16384, &tmB, s * 32, bn, MB + s * 16);
        }
    }

    float acc[2][8][4];
    #pragma unroll
    for (int i = 0; i < 2; i++)
        #pragma unroll
        for (int j = 0; j < 8; j++)
            #pragma unroll
            for (int p = 0; p < 4; p++) acc[i][j][p] = 0.f;

    int st = 0, fph = 0, eph = 0;
    for (int ch = 0; ch < nch; ch++) {
        WAITP(MB + st * 16, (uint32_t)fph);
        const float* Ab = base + st * (STGB >> 2);
        const float* Bb = Ab + 4096;
        #pragma unroll
        for (int kp = 0; kp < 2; kp++) {
            int s4 = t4 * 8 + kp * 4;
            float4 a00 = ld4sw(Ab, wm * 32 + g,      s4);
            float4 a01 = ld4sw(Ab, wm * 32 + 8 + g,  s4);
            float4 a10 = ld4sw(Ab, wm * 32 + 16 + g, s4);
            float4 a11 = ld4sw(Ab, wm * 32 + 24 + g, s4);
            #pragma unroll
            for (int nt = 0; nt < 8; nt++) {
                float4 b4 = ld4sw(Bb, wn * 64 + nt * 8 + g, s4);
                mma8(acc[0][nt], fbits(a00.x), fbits(a01.x), fbits(a00.y), fbits(a01.y),
                     fbits(b4.x), fbits(b4.y));
                mma8(acc[0][nt], fbits(a00.z), fbits(a01.z), fbits(a00.w), fbits(a01.w),
                     fbits(b4.z), fbits(b4.w));
                mma8(acc[1][nt], fbits(a10.x), fbits(a11.x), fbits(a10.y), fbits(a11.y),
                     fbits(b4.x), fbits(b4.y));
                mma8(acc[1][nt], fbits(a10.z), fbits(a11.z), fbits(a10.w), fbits(a11.w),
                     fbits(b4.z), fbits(b4.w));
            }
        }
        MBARR(MB + st * 16 + 8);
        if (tid == 0 && ch + NSTG < nch) {
            WAITP(MB + st * 16 + 8, (uint32_t)eph);
            EXPTX(MB + st * 16, STGB);
            TMA2D(sb + st * STGB,         &tmA, (ch + NSTG) * 32, bm, MB + st * 16);
            TMA2D(sb + st * STGB + 16384, &tmB, (ch + NSTG) * 32, bn, MB + st * 16);
        }
        if (++st == NSTG) { st = 0; fph ^= 1; eph ^= 1; }
    }

    #pragma unroll
    for (int mt = 0; mt < 2; mt++) {
        #pragma unroll
        for (int nt = 0; nt < 8; nt++) {
            int row = bm + wm * 32 + mt * 16 + g;
            int col = colOff + bn + wn * 64 + nt * 8 + 2 * t4;
            float v[4];
            #pragma unroll
            for (int p = 0; p < 4; p++) {
                float xv = acc[mt][nt][p];
                if (EPI == 3) {
                    if (col < 4096) { float rr = fmaxf(xv, 0.f); xv = rr * rr; }
                    else xv = 1.f / (1.f + __expf(-xv));
                }
                v[p] = xv;
            }
            *(float2*)&Cout[(size_t)row * ldC + col] = make_float2(v[0], v[1]);
            *(float2*)&Cout[(size_t)(row + 8) * ldC + col] = make_float2(v[2], v[3]);
        }
    }
}

// ---------------- rmsnorm (writes tf32-rounded, k-permuted) ----------------
__global__ void k_rmsnorm(const float* __restrict__ x, float* __restrict__ y) {
    int t = blockIdx.x;
    __shared__ float sx[C];
    __shared__ float red[8];
    const float* xr = x + (size_t)t * C;
    float ss = 0.f;
    for (int i = threadIdx.x; i < C; i += 256) { float v = xr[i]; sx[i] = v; ss += v * v; }
    #pragma unroll
    for (int o = 16; o; o >>= 1) ss += __shfl_xor_sync(0xffffffffu, ss, o);
    if ((threadIdx.x & 31) == 0) red[threadIdx.x >> 5] = ss;
    __syncthreads();
    if (threadIdx.x < 8) {
        float v = red[threadIdx.x];
        #pragma unroll
        for (int o = 4; o; o >>= 1) v += __shfl_xor_sync(0xffu, v, o);
        if (threadIdx.x == 0) red[0] = v;
    }
    __syncthreads();
    float sc = rsqrtf(red[0] / (float)C + 1e-6f);
    float* yr = y + (size_t)t * C;
    for (int i = threadIdx.x; i < C; i += 256) yr[pslot(i)] = tf32r(sx[i] * sc);
}

// ---------------- gate + rope + per-head rmsnorm ----------------
__global__ void k_ropegate(float* __restrict__ QKV, const float* __restrict__ XN,
                           const float* __restrict__ ve, const float* __restrict__ cosb,
                           const float* __restrict__ sinb, const float* __restrict__ wveg) {
    int t = blockIdx.x;
    int tt = t & (T - 1);
    __shared__ float sq[NH * HD];
    __shared__ float sr[NH * HD];
    __shared__ float gsm[NKV];
    int tid = threadIdx.x;
    float* Qb = QKV + (size_t)t * QKVW;
    float* Kb = Qb + 1024;
    float* Vb = Qb + 1280;
    if (tid < NKV) {
        float s = 0.f;
        #pragma unroll
        for (int j = 0; j < VECH; j++)
            s += XN[(size_t)t * C + ((j & 3) << 3) + (j >> 2)] * wveg[tid * VECH + j];
        gsm[tid] = 3.f / (1.f + __expf(-s));
    }
    for (int i = tid; i < NH * HD; i += 256) sq[i] = Qb[i];
    __syncthreads();
    for (int i = tid; i < NH * HD; i += 256) {
        int hh = i >> 6, d = i & 63;
        float val;
        if (d < 32) {
            float cv = cosb[tt * 32 + d], sv = sinb[tt * 32 + d];
            val = sq[hh * 64 + d] * cv + sq[hh * 64 + d + 32] * sv;
        } else {
            int d2 = d - 32;
            float cv = cosb[tt * 32 + d2], sv = sinb[tt * 32 + d2];
            val = -sq[hh * 64 + d2] * sv + sq[hh * 64 + d] * cv;
        }
        sr[i] = val;
    }
    __syncthreads();
    int w = tid >> 5, lane = tid & 31;
    for (int hh = w; hh < NH; hh += 8) {
        float v0 = sr[hh * 64 + lane], v1 = sr[hh * 64 + 32 + lane];
        float ss = v0 * v0 + v1 * v1;
        #pragma unroll
        for (int o = 16; o; o >>= 1) ss += __shfl_xor_sync(0xffffffffu, ss, o);
        float sc = rsqrtf(ss / 64.f + 1e-6f) * 1.2f;
        Qb[hh * 64 + lane] = v0 * sc;
        Qb[hh * 64 + 32 + lane] = v1 * sc;
    }
    __syncthreads();
    for (int i = tid; i < NKV * HD; i += 256) sq[i] = Kb[i];
    __syncthreads();
    for (int i = tid; i < NKV * HD; i += 256) {
        int hh = i >> 6, d = i & 63;
        float val;
        if (d < 32) {
            float cv = cosb[tt * 32 + d], sv = sinb[tt * 32 + d];
            val = sq[hh * 64 + d] * cv + sq[hh * 64 + d + 32] * sv;
        } else {
            int d2 = d - 32;
            float cv = cosb[tt * 32 + d2], sv = sinb[tt * 32 + d2];
            val = -sq[hh * 64 + d2] * sv + sq[hh * 64 + d] * cv;
        }
        sr[i] = val;
    }
    __syncthreads();
    if (w < NKV) {
        int hh = w;
        float v0 = sr[hh * 64 + lane], v1 = sr[hh * 64 + 32 + lane];
        float ss = v0 * v0 + v1 * v1;
        #pragma unroll
        for (int o = 16; o; o >>= 1) ss += __shfl_xor_sync(0xffffffffu, ss, o);
        float sc = rsqrtf(ss / 64.f + 1e-6f) * 1.2f;
        Kb[hh * 64 + lane] = v0 * sc;
        Kb[hh * 64 + 32 + lane] = v1 * sc;
    }
    {
        Vb[tid] = Vb[tid] + gsm[tid >> 6] * ve[(size_t)t * (NKV * HD) + tid];
    }
}

// ---------------- flash attention (Y written permuted) ----------------
__global__ void __launch_bounds__(256) k_flash(const float* __restrict__ QKV, const float* __restrict__ prev,
                        const float* __restrict__ rw, const float* __restrict__ alphap,
                        float* __restrict__ Y) {
    extern __shared__ float smf[];
    float* Qs = smf;
    float* KS = Qs + 64 * 68;
    float* Vt = KS + 64 * 68;
    float* Ps = Vt + 64 * 68;
    float* mrow = Ps + 66 * 66;
    float* lrow = mrow + 64;
    float* crow = lrow + 64;
    int tid = threadIdx.x, lane = tid & 31, w = tid >> 5;
    int g = lane >> 2, t4 = lane & 3;
    int wm = w >> 1, wn = w & 1;
    int qt = gridDim.x - 1 - blockIdx.x;
    int h = blockIdx.y, b = blockIdx.z;
    int q0 = qt * 64, hk = h >> 2;
    float alpha = alphap[0];
    float w9[9];
    #pragma unroll
    for (int i = 0; i < 9; i++) w9[i] = rw[h * 9 + i];

    for (int i = tid; i < 1024; i += 256) {
        int rr = i >> 4, d4 = (i & 15) << 2;
        float4 qv = *(const float4*)&QKV[((size_t)(b * T) + q0 + rr) * QKVW + h * 64 + d4];
        Qs[rr * 68 + pslot(d4 + 0)] = qv.x;
        Qs[rr * 68 + pslot(d4 + 1)] = qv.y;
        Qs[rr * 68 + pslot(d4 + 2)] = qv.z;
        Qs[rr * 68 + pslot(d4 + 3)] = qv.w;
    }
    if (tid < 64) { mrow[tid] = -INFINITY; lrow[tid] = 0.f; }
    float o[4][4];
    #pragma unroll
    for (int i = 0; i < 4; i++)
        #pragma unroll
        for (int j = 0; j < 4; j++) o[i][j] = 0.f;

    for (int kt = 0; kt <= qt; kt++) {
        int k0 = kt * 64;
        __syncthreads();
        for (int i = tid; i < 1024; i += 256) {
            int rr = i >> 4, d4 = (i & 15) << 2;
            const float* basep = &QKV[((size_t)(b * T) + k0 + rr) * QKVW];
            float4 kv = *(const float4*)&basep[1024 + hk * 64 + d4];
            KS[rr * 68 + pslot(d4 + 0)] = kv.x;
            KS[rr * 68 + pslot(d4 + 1)] = kv.y;
            KS[rr * 68 + pslot(d4 + 2)] = kv.z;
            KS[rr * 68 + pslot(d4 + 3)] = kv.w;
            float4 vv = *(const float4*)&basep[1280 + hk * 64 + d4];
            int pr = pslot(rr);
            Vt[(d4 + 0) * 68 + pr] = vv.x;
            Vt[(d4 + 1) * 68 + pr] = vv.y;
            Vt[(d4 + 2) * 68 + pr] = vv.z;
            Vt[(d4 + 3) * 68 + pr] = vv.w;
        }
        for (int idx = tid; idx < 66 * 66; idx += 256) {
            int li = idx / 66, lj = idx - li * 66;
            int gi = q0 - 1 + li, gj = k0 - 1 + lj;
            float v = 0.f;
            if (gi >= 0 && gi < T && gj >= 0 && gj < T)
                v = prev[(((size_t)(b * NH) + h) * T + gi) * T + gj];
            Ps[idx] = v;
        }
        __syncthreads();
        float sacc[4][4];
        #pragma unroll
        for (int i = 0; i < 4; i++)
            #pragma unroll
            for (int j = 0; j < 4; j++) sacc[i][j] = 0.f;
        #pragma unroll
        for (int kp = 0; kp < 4; kp++) {
            int koff = (kp >> 1) * 32 + t4 * 8 + (kp & 1) * 4;
            float4 af0 = *(float4*)&Qs[(wm * 16 + g) * 68 + koff];
            float4 af1 = *(float4*)&Qs[(wm * 16 + 8 + g) * 68 + koff];
            float4 bf[4];
            #pragma unroll
            for (int nt = 0; nt < 4; nt++)
                bf[nt] = *(float4*)&KS[(wn * 32 + nt * 8 + g) * 68 + koff];
            #pragma unroll
            for (int kk = 0; kk < 2; kk++) {
                unsigned a0 = fbits(kk ? af0.z : af0.x), a2 = fbits(kk ? af0.w : af0.y);
                unsigned a1 = fbits(kk ? af1.z : af1.x), a3 = fbits(kk ? af1.w : af1.y);
                #pragma unroll
                for (int nt = 0; nt < 4; nt++) {
                    unsigned b0 = fbits(kk ? bf[nt].z : bf[nt].x);
                    unsigned b1 = fbits(kk ? bf[nt].w : bf[nt].y);
                    mma8(sacc[nt], a0, a1, a2, a3, b0, b1);
                }
            }
        }
        __syncthreads();
        #pragma unroll
        for (int nt = 0; nt < 4; nt++) {
            #pragma unroll
            for (int rg = 0; rg < 2; rg++) {
                int ri = wm * 16 + g + rg * 8;
                int cj = wn * 32 + nt * 8 + 2 * t4;
                float p[3][4];
                #pragma unroll
                for (int a = 0; a < 3; a++) {
                    float2 x0 = *(float2*)&Ps[(ri + a) * 66 + cj];
                    float2 x1 = *(float2*)&Ps[(ri + a) * 66 + cj + 2];
                    p[a][0] = x0.x; p[a][1] = x0.y; p[a][2] = x1.x; p[a][3] = x1.y;
                }
                float cv0 = 0.f, cv1 = 0.f;
                #pragma unroll
                for (int a = 0; a < 3; a++)
                    #pragma unroll
                    for (int bb = 0; bb < 3; bb++) {
                        cv0 = fmaf(w9[a * 3 + bb], p[a][bb], cv0);
                        cv1 = fmaf(w9[a * 3 + bb], p[a][bb + 1], cv1);
                    }
                float v0 = sacc[nt][rg * 2 + 0] * 0.125f + alpha * cv0;
                float v1 = sacc[nt][rg * 2 + 1] * 0.125f + alpha * cv1;
                if (k0 + cj > q0 + ri) v0 = -INFINITY;
                if (k0 + cj + 1 > q0 + ri) v1 = -INFINITY;
                KS[ri * 68 + pslot(cj)] = v0;
                KS[ri * 68 + pslot(cj + 1)] = v1;
            }
        }
        __syncthreads();
        {
            int row = tid >> 2, part = tid & 3;
            float* srow = KS + row * 68 + part * 16;
            float4 s0 = *(float4*)&srow[0], s1 = *(float4*)&srow[4];
            float4 s2 = *(float4*)&srow[8], s3 = *(float4*)&srow[12];
            float rm = fmaxf(fmaxf(fmaxf(s0.x, s0.y), fmaxf(s0.z, s0.w)),
                             fmaxf(fmaxf(s1.x, s1.y), fmaxf(s1.z, s1.w)));
            rm = fmaxf(rm, fmaxf(fmaxf(fmaxf(s2.x, s2.y), fmaxf(s2.z, s2.w)),
                                 fmaxf(fmaxf(s3.x, s3.y), fmaxf(s3.z, s3.w))));
            rm = fmaxf(rm, __shfl_xor_sync(0xffffffffu, rm, 1));
            rm = fmaxf(rm, __shfl_xor_sync(0xffffffffu, rm, 2));
            float mo = mrow[row];
            float nm = fmaxf(mo, rm);
            float sum = 0.f;
            #define EXA(v) v.x = __expf(v.x - nm); v.y = __expf(v.y - nm); \
                           v.z = __expf(v.z - nm); v.w = __expf(v.w - nm); \
                           sum += v.x + v.y + v.z + v.w;
            EXA(s0) EXA(s1) EXA(s2) EXA(s3)
            #undef EXA
            *(float4*)&srow[0] = s0; *(float4*)&srow[4] = s1;
            *(float4*)&srow[8] = s2; *(float4*)&srow[12] = s3;
            sum += __shfl_xor_sync(0xffffffffu, sum, 1);
            sum += __shfl_xor_sync(0xffffffffu, sum, 2);
            if (part == 0) {
                float corr = __expf(mo - nm);
                mrow[row] = nm;
                lrow[row] = lrow[row] * corr + sum;
                crow[row] = corr;
            }
        }
        __syncthreads();
        float c0 = crow[wm * 16 + g], c1 = crow[wm * 16 + 8 + g];
        #pragma unroll
        for (int nt = 0; nt < 4; nt++) {
            o[nt][0] *= c0; o[nt][1] *= c0; o[nt][2] *= c1; o[nt][3] *= c1;
        }
        #pragma unroll
        for (int kp = 0; kp < 4; kp++) {
            int koff = (kp >> 1) * 32 + t4 * 8 + (kp & 1) * 4;
            float4 af0 = *(float4*)&KS[(wm * 16 + g) * 68 + koff];
            float4 af1 = *(float4*)&KS[(wm * 16 + 8 + g) * 68 + koff];
            float4 bf[4];
            #pragma unroll
            for (int nt = 0; nt < 4; nt++)
                bf[nt] = *(float4*)&Vt[(wn * 32 + nt * 8 + g) * 68 + koff];
            #pragma unroll
            for (int kk = 0; kk < 2; kk++) {
                unsigned a0 = fbits(kk ? af0.z : af0.x), a2 = fbits(kk ? af0.w : af0.y);
                unsigned a1 = fbits(kk ? af1.z : af1.x), a3 = fbits(kk ? af1.w : af1.y);
                #pragma unroll
                for (int nt = 0; nt < 4; nt++) {
                    unsigned b0 = fbits(kk ? bf[nt].z : bf[nt].x);
                    unsigned b1 = fbits(kk ? bf[nt].w : bf[nt].y);
                    mma8(o[nt], a0, a1, a2, a3, b0, b1);
                }
            }
        }
    }
    {
        float inv0 = 1.f / lrow[wm * 16 + g];
        float inv1 = 1.f / lrow[wm * 16 + 8 + g];
        int r0 = q0 + wm * 16 + g;
        #pragma unroll
        for (int nt = 0; nt < 4; nt++) {
            int cj = wn * 32 + nt * 8 + 2 * t4;
            int c0i = h * 64 + cj;
            Y[((size_t)(b * T) + r0) * C + pslot(c0i)] = o[nt][0] * inv0;
            Y[((size_t)(b * T) + r0) * C + pslot(c0i + 1)] = o[nt][1] * inv0;
            Y[((size_t)(b * T) + r0 + 8) * C + pslot(c0i)] = o[nt][2] * inv1;
            Y[((size_t)(b * T) + r0 + 8) * C + pslot(c0i + 1)] = o[nt][3] * inv1;
        }
    }
}

// ---------------- small kernels ----------------
__global__ void k_dot32(const float* __restrict__ X, const float* __restrict__ W,
                        float* __restrict__ OUT) {
    __shared__ float sx[8 * C];
    int t0 = blockIdx.x * 8;
    for (int i = threadIdx.x; i < 8 * C; i += 256) sx[i] = X[(size_t)t0 * C + i];
    __syncthreads();
    int tok = threadIdx.x >> 5, oo = threadIdx.x & 31;
    const float4* wr = (const float4*)(W + (size_t)oo * C);
    const float4* xr = (const float4*)(sx + tok * C);
    float s = 0.f;
    #pragma unroll 4
    for (int k = 0; k < C / 4; k++) {
        float4 a = xr[k], b = wr[k];
        s += a.x * b.x + a.y * b.y + a.z * b.z + a.w * b.w;
    }
    OUT[(size_t)(t0 + tok) * CADIM + oo] = s;
}

__global__ void k_caconv(const float* __restrict__ R, const float* __restrict__ cw,
                         float* __restrict__ OUT) {
    int b = blockIdx.y, t0 = blockIdx.x * 128;
    __shared__ float s[130 * 32];
    __shared__ float w[32 * 3];
    for (int i = threadIdx.x; i < 96; i += 256) w[i] = cw[i];
    for (int i = threadIdx.x; i < 130 * 32; i += 256) {
        int r = i >> 5, c = i & 31;
        int t = t0 - 1 + r;
        s[i] = (t >= 0 && t < T) ? R[((size_t)(b * T) + t) * CADIM + c] : 0.f;
    }
    __syncthreads();
    for (int i = threadIdx.x; i < 128 * 32; i += 256) {
        int r = i >> 5, c = i & 31;
        float h0 = s[(r + 1) * 32 + c];
        float cv = w[c * 3 + 0] * s[r * 32 + c] + w[c * 3 + 1] * h0 + w[c * 3 + 2] * s[(r + 2) * 32 + c];
        float v = h0 + 0.1f * cv;
        v = 0.5f * v * (1.f + erff(v * 0.70710678118f));
        OUT[((size_t)(b * T) + t0 + r) * CADIM + c] = v;
    }
}

__global__ void k_x1(const float* __restrict__ x, const float* __restrict__ attn,
                     const float* __restrict__ cah, const float* __restrict__ capo,
                     float* __restrict__ X1) {
    int tg = blockIdx.x;
    __shared__ float h[16 * 32];
    __shared__ float po[256 * 33];
    int tid = threadIdx.x;
    for (int i = tid; i < 16 * 32; i += 256) h[i] = cah[(size_t)tg * 16 * 32 + i];
    for (int cc = 0; cc < 4; cc++) {
        int c0 = cc * 256;
        __syncthreads();
        for (int i = tid; i < 256 * 32; i += 256) po[(i >> 5) * 33 + (i & 31)] = capo[(size_t)c0 * 32 + i];
        __syncthreads();
        float wv[32];
        #pragma unroll
        for (int j = 0; j < 32; j++) wv[j] = po[tid * 33 + j];
        int c = c0 + tid;
        for (int tok = 0; tok < 16; tok++) {
            float ca = 0.f;
            #pragma unroll
            for (int j = 0; j < 32; j++) ca = fmaf(wv[j], h[tok * 32 + j], ca);
            size_t idx = ((size_t)tg * 16 + tok) * C + c;
            X1[idx] = x[idx] + attn[idx] * (1.f + 0.1f * tanhf(ca));
        }
    }
}

// FFN depthwise conv, 4 fused iterations; reads HG(stride FW), writes H2 permuted+rounded
__global__ void k_ffnconv(const float* __restrict__ Hin, const float* __restrict__ cw,
                          float* __restrict__ Hout) {
    int c0 = blockIdx.x * 32, t0 = blockIdx.y * 64, b = blockIdx.z;
    __shared__ float bufA[72 * 32];
    __shared__ float bufB[72 * 32];
    __shared__ float w[32 * 3];
    int tid = threadIdx.x;
    for (int i = tid; i < 96; i += 256) w[i] = cw[(size_t)c0 * 3 + i];
    for (int i = tid; i < 72 * 32; i += 256) {
        int r = i >> 5, c = i & 31;
        int t = t0 - 4 + r;
        bufA[i] = (t >= 0 && t < T) ? Hin[((size_t)(b * T) + t) * FW + c0 + c] : 0.f;
    }
    float* A = bufA;
    float* Bf = bufB;
    for (int it = 0; it < 4; it++) {
        __syncthreads();
        for (int i = tid; i < 72 * 32; i += 256) {
            int r = i >> 5, c = i & 31;
            int t = t0 - 4 + r;
            float v = 0.f;
            if (t >= 0 && t < T) {
                float am = (r > 0) ? A[(r - 1) * 32 + c] : 0.f;
                float a0 = A[i];
                float ap = (r < 71) ? A[(r + 1) * 32 + c] : 0.f;
                v = a0 + 0.1f * (w[c * 3] * am + w[c * 3 + 1] * a0 + w[c * 3 + 2] * ap);
            }
            Bf[i] = v;
        }
        float* tmp = A; A = Bf; Bf = tmp;
    }
    __syncthreads();
    for (int i = tid; i < 64 * 32; i += 256) {
        int r = i >> 5, c = i & 31;
        int s = c0 + ((c & 3) << 3) + (c >> 2);
        Hout[((size_t)(b * T) + t0 + r) * FFNH + s] = tf32r(A[(r + 4) * 32 + c]);
    }
}

__global__ void k_vitpost(const float* __restrict__ VR, const float* __restrict__ w2,
                          float* __restrict__ VIT) {
    int t = blockIdx.x * 256 + threadIdx.x;
    float s = 0.f;
    #pragma unroll
    for (int j = 0; j < 32; j++) {
        float v = VR[(size_t)t * 32 + j];
        v = 0.5f * v * (1.f + erff(v * 0.70710678118f));
        s += v * w2[j];
    }
    VIT[t] = 1.f / (1.f + __expf(-s));
}

__global__ void k_vsmooth(const float* __restrict__ VIT, float* __restrict__ VITF) {
    int b = blockIdx.x;
    for (int t = threadIdx.x; t < T; t += 256) {
        float v = VIT[b * T + t];
        float s = 0.f;
        #pragma unroll
        for (int d = -2; d <= 2; d++) {
            int tt = t + d;
            if (tt >= 0 && tt < T) s += VIT[b * T + tt];
        }
        s *= 0.2f;
        float f = 0.7f * v + 0.3f * s;
        VITF[b * T + t] = (f > 0.3f) ? f : 0.1f * f;
    }
}

__global__ void k_final(const float* __restrict__ x1, const float* __restrict__ mlp,
                        const float* __restrict__ HG, const float* __restrict__ cah,
                        const float* __restrict__ capo, const float* __restrict__ vitf,
                        float* __restrict__ out) {
    int tg = blockIdx.x;
    __shared__ float h[16 * 32];
    __shared__ float po[256 * 33];
    __shared__ float sv[16];
    int tid = threadIdx.x;
    for (int i = tid; i < 16 * 32; i += 256) h[i] = cah[(size_t)tg * 16 * 32 + i];
    if (tid < 16) sv[tid] = vitf[tg * 16 + tid];
    for (int cc = 0; cc < 4; cc++) {
        int c0 = cc * 256;
        __syncthreads();
        for (int i = tid; i < 256 * 32; i += 256) po[(i >> 5) * 33 + (i & 31)] = capo[(size_t)c0 * 32 + i];
        __syncthreads();
        float wv[32];
        #pragma unroll
        for (int j = 0; j < 32; j++) wv[j] = po[tid * 33 + j];
        int c = c0 + tid;
        for (int tok = 0; tok < 16; tok++) {
            float ca = 0.f;
            #pragma unroll
            for (int j = 0; j < 32; j++) ca = fmaf(wv[j], h[tok * 32 + j], ca);
            size_t idx = ((size_t)tg * 16 + tok) * C + c;
            float gate = HG[((size_t)tg * 16 + tok) * FW + 4096 + c];
            float m = mlp[idx] * gate * (1.f + 0.1f * tanhf(ca)) * sv[tok];
            out[idx] = x1[idx] + m;
        }
    }
}

// ---------------- host ----------------
typedef CUresult (*PFN_tmenc)(CUtensorMap*, CUtensorMapDataType, cuuint32_t, void*,
                              const cuuint64_t*, const cuuint64_t*, const cuuint32_t*,
                              const cuuint32_t*, CUtensorMapInterleave, CUtensorMapSwizzle,
                              CUtensorMapL2promotion, CUtensorMapFloatOOBfill);
static PFN_tmenc tmenc() {
    static PFN_tmenc fp = nullptr;
    if (!fp) {
        void* p = nullptr;
        cudaDriverEntryPointQueryResult qr;
        cudaGetDriverEntryPoint("cuTensorMapEncodeTiled", &p, cudaEnableDefault, &qr);
        fp = (PFN_tmenc)p;
    }
    return fp;
}
static void mk_tmap(CUtensorMap* m, const void* ptr, int M, int K) {
    cuuint64_t dims[2] = {(cuuint64_t)K, (cuuint64_t)M};
    cuuint64_t strides[1] = {(cuuint64_t)K * 4};
    cuuint32_t box[2] = {32, 128};
    cuuint32_t es[2] = {1, 1};
    tmenc()(m, CU_TENSOR_MAP_DATA_TYPE_FLOAT32, 2, (void*)ptr, dims, strides, box, es,
            CU_TENSOR_MAP_INTERLEAVE_NONE, CU_TENSOR_MAP_SWIZZLE_128B,
            CU_TENSOR_MAP_L2_PROMOTION_L2_128B, CU_TENSOR_MAP_FLOAT_OOB_FILL_NONE);
}

extern "C" void kernel_launch(void* const* d_in, const int* in_sizes, int n_in,
                              void* d_out, int out_size) {
    const float* x        = (const float*)d_in[0];
    const float* ve       = (const float*)d_in[1];
    const float* cosb     = (const float*)d_in[2];
    const float* sinb     = (const float*)d_in[3];
    const float* prev     = (const float*)d_in[4];
    const float* w_q      = (const float*)d_in[5];
    const float* w_k      = (const float*)d_in[6];
    const float* w_v      = (const float*)d_in[7];
    const float* w_o      = (const float*)d_in[8];
    const float* w_veg    = (const float*)d_in[9];
    const float* refine_w = (const float*)d_in[10];
    const float* alpha    = (const float*)d_in[11];
    const float* ca_pi    = (const float*)d_in[12];
    const float* ca_cw    = (const float*)d_in[13];
    const float* ca_po    = (const float*)d_in[14];
    const float* ffn_in   = (const float*)d_in[15];
    const float* ffn_cw   = (const float*)d_in[16];
    const float* ffn_out  = (const float*)d_in[17];
    const float* ffn_gate = (const float*)d_in[18];
    const float* vit_w1   = (const float*)d_in[19];
    const float* vit_w2   = (const float*)d_in[20];
    float* out = (float*)d_out;

    float *XN, *QKV, *Yp, *ATT, *X1, *XM, *HG, *H2, *MLP, *CR1, *CA1, *CR2, *CA2, *VR, *VIT, *VITF;
    float *WQKVp, *WOp, *WFp, *WFOp;
    cudaGetSymbolAddress((void**)&XN, g_XN);
    cudaGetSymbolAddress((void**)&QKV, g_QKV);
    cudaGetSymbolAddress((void**)&Yp, g_Y);
    cudaGetSymbolAddress((void**)&ATT, g_ATT);
    cudaGetSymbolAddress((void**)&X1, g_X1);
    cudaGetSymbolAddress((void**)&XM, g_XM);
    cudaGetSymbolAddress((void**)&HG, g_HG);
    cudaGetSymbolAddress((void**)&H2, g_H2);
    cudaGetSymbolAddress((void**)&MLP, g_MLP);
    cudaGetSymbolAddress((void**)&CR1, g_CR1);
    cudaGetSymbolAddress((void**)&CA1, g_CA1);
    cudaGetSymbolAddress((void**)&CR2, g_CR2);
    cudaGetSymbolAddress((void**)&CA2, g_CA2);
    cudaGetSymbolAddress((void**)&VR, g_VR);
    cudaGetSymbolAddress((void**)&VIT, g_VIT);
    cudaGetSymbolAddress((void**)&VITF, g_VITF);
    cudaGetSymbolAddress((void**)&WQKVp, g_WQKVp);
    cudaGetSymbolAddress((void**)&WOp, g_WOp);
    cudaGetSymbolAddress((void**)&WFp, g_WFp);
    cudaGetSymbolAddress((void**)&WFOp, g_WFOp);

    static CUtensorMap tXN, tWQKV, tY, tWO, tXM, tWF, tH2, tWFO;
    mk_tmap(&tXN, XN, BT, C);
    mk_tmap(&tWQKV, WQKVp, QKVW, C);
    mk_tmap(&tY, Yp, BT, C);
    mk_tmap(&tWO, WOp, 1024, C);
    mk_tmap(&tXM, XM, BT, C);
    mk_tmap(&tWF, WFp, FW, C);
    mk_tmap(&tH2, H2, BT, FFNH);
    mk_tmap(&tWFO, WFOp, 1024, FFNH);

    cudaFuncSetAttribute(k_tgemm<0>, cudaFuncAttributeMaxDynamicSharedMemorySize, TG_SMEM);
    cudaFuncSetAttribute(k_tgemm<3>, cudaFuncAttributeMaxDynamicSharedMemorySize, TG_SMEM);
    const int smemf = (3 * 64 * 68 + 66 * 66 + 3 * 64) * (int)sizeof(float);
    cudaFuncSetAttribute(k_flash, cudaFuncAttributeMaxDynamicSharedMemorySize, smemf);

    // streams/events: created on the (uncaptured) correctness call, reused during capture
    static cudaStream_t sA = nullptr, sB = nullptr;
    static cudaEvent_t eF, eWqkv, eWrest, eCA1, eX1, eS2, eEnd;
    if (!sA) {
        cudaStreamCreateWithFlags(&sA, cudaStreamNonBlocking);
        cudaStreamCreateWithFlags(&sB, cudaStreamNonBlocking);
        cudaEventCreateWithFlags(&eF, cudaEventDisableTiming);
        cudaEventCreateWithFlags(&eWqkv, cudaEventDisableTiming);
        cudaEventCreateWithFlags(&eWrest, cudaEventDisableTiming);
        cudaEventCreateWithFlags(&eCA1, cudaEventDisableTiming);
        cudaEventCreateWithFlags(&eX1, cudaEventDisableTiming);
        cudaEventCreateWithFlags(&eS2, cudaEventDisableTiming);
        cudaEventCreateWithFlags(&eEnd, cudaEventDisableTiming);
    }

    // fork from the captured stream
    cudaEventRecord(eF, 0);
    cudaStreamWaitEvent(sA, eF, 0);
    cudaStreamWaitEvent(sB, eF, 0);

    // [1] sA: rmsnorm
    k_rmsnorm<<<BT, 256, 0, sA>>>(x, XN);
    // [2-4] sB: permw q,k,v into fused buffer
    k_permw4<<<(1024 * 256 + 255) / 256, 256, 0, sB>>>(w_q, WQKVp, 1024 * 256, 1023);
    k_permw4<<<(256 * 256 + 255) / 256, 256, 0, sB>>>(w_k, WQKVp + 1024 * C, 256 * 256, 1023);
    k_permw4<<<(256 * 256 + 255) / 256, 256, 0, sB>>>(w_v, WQKVp + 1280 * C, 256 * 256, 1023);
    cudaEventRecord(eWqkv, sB);
    // [5] sB: ca1 projection on x (independent)
    k_dot32<<<BT / 8, 256, 0, sB>>>(x, ca_pi, CR1);
    // [6] sA: fused QKV GEMM  (profiled launch)
    cudaStreamWaitEvent(sA, eWqkv, 0);
    k_tgemm<0><<<dim3(QKVW / 128, 32), 256, TG_SMEM, sA>>>(tXN, tWQKV, QKV, QKVW, 0, C);
    // sB: rest of permw + ca1 conv
    k_caconv<<<dim3(T / 128, BB), 256, 0, sB>>>(CR1, ca_cw, CA1);
    cudaEventRecord(eCA1, sB);
    k_permw4<<<(1024 * 256 + 255) / 256, 256, 0, sB>>>(w_o, WOp, 1024 * 256, 1023);
    k_permw4<<<(4096 * 256 + 255) / 256, 256, 0, sB>>>(ffn_in, WFp, 4096 * 256, 1023);
    k_permw4<<<(1024 * 256 + 255) / 256, 256, 0, sB>>>(ffn_gate, WFp + (size_t)4096 * C, 1024 * 256, 1023);
    k_permw4<<<(1024 * 1024 + 255) / 256, 256, 0, sB>>>(ffn_out, WFOp, 1024 * 1024, 4095);
    cudaEventRecord(eWrest, sB);

    // sA: attention chain
    k_ropegate<<<BT, 256, 0, sA>>>(QKV, XN, ve, cosb, sinb, w_veg);
    k_flash<<<dim3(T / 64, NH, BB), 256, smemf, sA>>>(QKV, prev, refine_w, alpha, Yp);
    cudaStreamWaitEvent(sA, eWrest, 0);
    k_tgemm<0><<<dim3(8, 32), 256, TG_SMEM, sA>>>(tY, tWO, ATT, C, 0, C);
    cudaStreamWaitEvent(sA, eCA1, 0);
    k_x1<<<BT / 16, 256, 0, sA>>>(x, ATT, CA1, ca_po, X1);
    cudaEventRecord(eX1, sA);

    // sA: FFN chain
    k_rmsnorm<<<BT, 256, 0, sA>>>(X1, XM);
    k_tgemm<3><<<dim3(FW / 128, 32), 256, TG_SMEM, sA>>>(tXM, tWF, HG, FW, 0, C);
    // sB: ca2 + vit chains (depend on X1)
    cudaStreamWaitEvent(sB, eX1, 0);
    k_dot32<<<BT / 8, 256, 0, sB>>>(X1, ca_pi, CR2);
    k_caconv<<<dim3(T / 128, BB), 256, 0, sB>>>(CR2, ca_cw, CA2);
    k_dot32<<<BT / 8, 256, 0, sB>>>(X1, vit_w1, VR);
    k_vitpost<<<BT / 256, 256, 0, sB>>>(VR, vit_w2, VIT);
    k_vsmooth<<<BB, 256, 0, sB>>>(VIT, VITF);
    cudaEventRecord(eS2, sB);

    k_ffnconv<<<dim3(FFNH / 32, T / 64, BB), 256, 0, sA>>>(HG, ffn_cw, H2);
    k_tgemm<0><<<dim3(8, 32), 256, TG_SMEM, sA>>>(tH2, tWFO, MLP, C, 0, FFNH);
    cudaStreamWaitEvent(sA, eS2, 0);
    k_final<<<BT / 16, 256, 0, sA>>>(X1, MLP, HG, CA2, ca_po, VITF, out);

    // join back into the captured stream
    cudaEventRecord(eEnd, sA);
    cudaStreamWaitEvent(0, eEnd, 0);
}

// round 15
// speedup vs baseline: 1.0847x; 1.0031x over previous
#include <cuda_runtime.h>
#include <cuda.h>
#include <math.h>

#define BB 4
#define T 1024
#define C 1024
#define BT (BB*T)
#define NH 16
#define NKV 4
#define HD 64
#define FFNH 4096
#define CADIM 32
#define VECH 12
#define QKVW 1536
#define FW 5120

// ---------------- scratch ----------------
__device__ float g_XN[BT*C];
__device__ float g_QKV[BT*QKVW];
__device__ float g_Y[BT*C];
__device__ float g_ATT[BT*C];
__device__ float g_X1[BT*C];
__device__ float g_XM[BT*C];
__device__ float g_HG[(size_t)BT*FW];
__device__ float g_H2[(size_t)BT*FFNH];
__device__ float g_MLP[BT*C];
__device__ float g_CR1[BT*CADIM];
__device__ float g_CA1[BT*CADIM];
__device__ float g_CR2[BT*CADIM];
__device__ float g_CA2[BT*CADIM];
__device__ float g_VR[BT*CADIM];
__device__ float g_VIT[BT];
__device__ float g_VITF[BT];
// permuted weights (fused)
__device__ float g_WQKVp[(size_t)QKVW*C];
__device__ float g_WOp[C*C];
__device__ float g_WFp[(size_t)FW*C];
__device__ float g_WFOp[(size_t)C*FFNH];

// ---------------- helpers ----------------
__device__ __forceinline__ unsigned fbits(float x) { return __float_as_uint(x); }
__device__ __forceinline__ float tf32r(float x) {
    unsigned u; asm("cvt.rna.tf32.f32 %0, %1;" : "=r"(u) : "f"(x));
    return __uint_as_float(u);
}
__device__ __forceinline__ int pslot(int k) {
    return (k & ~31) | ((k & 3) << 3) | ((k & 31) >> 2);
}
__device__ __forceinline__ void mma8(float* c, unsigned a0, unsigned a1, unsigned a2, unsigned a3,
                                     unsigned b0, unsigned b1) {
    asm("mma.sync.aligned.m16n8k8.row.col.f32.tf32.tf32.f32 "
        "{%0,%1,%2,%3},{%4,%5,%6,%7},{%8,%9},{%0,%1,%2,%3};"
        : "+f"(c[0]), "+f"(c[1]), "+f"(c[2]), "+f"(c[3])
        : "r"(a0), "r"(a1), "r"(a2), "r"(a3), "r"(b0), "r"(b1));
}
#define MBINIT(addr, cnt) \
    asm volatile("mbarrier.init.shared.b64 [%0], %1;" :: "r"(addr), "r"((uint32_t)(cnt)) : "memory")
#define MBARR(addr) \
    asm volatile("mbarrier.arrive.shared.b64 _, [%0];" :: "r"(addr) : "memory")
#define EXPTX(addr, bytes) \
    asm volatile("mbarrier.arrive.expect_tx.shared.b64 _, [%0], %1;" :: "r"(addr), "r"((uint32_t)(bytes)) : "memory")
#define WAITP(addr, par) do { \
    uint32_t _m = (addr), _p = (par), _d; \
    asm volatile("{\n .reg .pred p;\n mbarrier.try_wait.parity.acquire.cta.shared::cta.b64 p, [%1], %2;\n selp.b32 %0,1,0,p;\n}" \
                 : "=r"(_d) : "r"(_m), "r"(_p) : "memory"); \
    if (!_d) { \
        asm volatile("{\n .reg .pred P1;\nWL_%=:\n mbarrier.try_wait.parity.acquire.cta.shared::cta.b64 P1, [%0], %1, 0x989680;\n @P1 bra.uni WD_%=;\n bra.uni WL_%=;\nWD_%=:\n}" \
                     :: "r"(_m), "r"(_p) : "memory"); \
    } } while (0)
#define TMA2D(saddr, map, cx, cy, mbar) \
    asm volatile("cp.async.bulk.tensor.2d.shared::cta.global.tile.mbarrier::complete_tx::bytes [%0], [%1, {%2, %3}], [%4];" \
                 :: "r"((uint32_t)(saddr)), "l"(map), "r"((int)(cx)), "r"((int)(cy)), "r"((uint32_t)(mbar)) : "memory")

__device__ __forceinline__ float4 ld4sw(const float* tile, int r, int slot4) {
    int off = (r * 128 + slot4 * 4) ^ ((r & 7) << 4);
    return *(const float4*)((const char*)tile + off);
}

// ---------------- weight permute + round ----------------
__global__ void k_permw4(const float* __restrict__ in, float* __restrict__ out, int n4, int kmask) {
    int i4 = blockIdx.x * 256 + threadIdx.x;
    if (i4 >= n4) return;
    int i = i4 * 4;
    float4 v = *(const float4*)&in[i];
    int k = i & kmask;
    int base = i - k;
    out[base + pslot(k + 0)] = tf32r(v.x);
    out[base + pslot(k + 1)] = tf32r(v.y);
    out[base + pslot(k + 2)] = tf32r(v.z);
    out[base + pslot(k + 3)] = tf32r(v.w);
}

// ---------------- TMA-fed tf32 GEMM (permuted operands) ----------------
// EPI: 0 none, 3 = (global col<4096 ? relu^2 : sigmoid)
#define STGB 32768
#define NSTG 3
#define TG_SMEM (1024 + NSTG * STGB + 64)

template<int EPI>
__global__ void __launch_bounds__(256, 2)
k_tgemm(const __grid_constant__ CUtensorMap tmA, const __grid_constant__ CUtensorMap tmB,
        float* __restrict__ Cout, int ldC, int colOff, int K) {
    extern __shared__ float smraw[];
    uint32_t sb0;
    asm("{ .reg .u64 t; cvta.to.shared.u64 t, %1; cvt.u32.u64 %0, t; }" : "=r"(sb0) : "l"(smraw));
    uint32_t sb = (sb0 + 1023) & ~1023u;
    uint32_t MB = sb + NSTG * STGB;
    const int tid = threadIdx.x, lane = tid & 31, w = tid >> 5;
    const int g = lane >> 2, t4 = lane & 3;
    const int wm = w >> 1, wn = w & 1;
    const int bm = blockIdx.y * 128, bn = blockIdx.x * 128;
    const int nch = K >> 5;
    const float* base = smraw + ((sb - sb0) >> 2);

    if (tid == 0)
        for (int s = 0; s < NSTG; s++) { MBINIT(MB + s * 16, 1); MBINIT(MB + s * 16 + 8, 256); }
    __syncthreads();
    if (tid == 0) {
        #pragma unroll
        for (int s = 0; s < NSTG; s++) {
            EXPTX(MB + s * 16, STGB);
            TMA2D(sb + s * STGB,         &tmA, s * 32, bm, MB + s * 16);
            TMA2D(sb + s * STGB + 16384, &tmB, s * 32, bn, MB + s * 16);
        }
    }

    float acc[2][8][4];
    #pragma unroll
    for (int i = 0; i < 2; i++)
        #pragma unroll
        for (int j = 0; j < 8; j++)
            #pragma unroll
            for (int p = 0; p < 4; p++) acc[i][j][p] = 0.f;

    int st = 0, fph = 0, eph = 0;
    for (int ch = 0; ch < nch; ch++) {
        WAITP(MB + st * 16, (uint32_t)fph);
        const float* Ab = base + st * (STGB >> 2);
        const float* Bb = Ab + 4096;
        #pragma unroll
        for (int kp = 0; kp < 2; kp++) {
            int s4 = t4 * 8 + kp * 4;
            float4 a00 = ld4sw(Ab, wm * 32 + g,      s4);
            float4 a01 = ld4sw(Ab, wm * 32 + 8 + g,  s4);
            float4 a10 = ld4sw(Ab, wm * 32 + 16 + g, s4);
            float4 a11 = ld4sw(Ab, wm * 32 + 24 + g, s4);
            #pragma unroll
            for (int nt = 0; nt < 8; nt++) {
                float4 b4 = ld4sw(Bb, wn * 64 + nt * 8 + g, s4);
                mma8(acc[0][nt], fbits(a00.x), fbits(a01.x), fbits(a00.y), fbits(a01.y),
                     fbits(b4.x), fbits(b4.y));
                mma8(acc[0][nt], fbits(a00.z), fbits(a01.z), fbits(a00.w), fbits(a01.w),
                     fbits(b4.z), fbits(b4.w));
                mma8(acc[1][nt], fbits(a10.x), fbits(a11.x), fbits(a10.y), fbits(a11.y),
                     fbits(b4.x), fbits(b4.y));
                mma8(acc[1][nt], fbits(a10.z), fbits(a11.z), fbits(a10.w), fbits(a11.w),
                     fbits(b4.z), fbits(b4.w));
            }
        }
        MBARR(MB + st * 16 + 8);
        if (tid == 0 && ch + NSTG < nch) {
            WAITP(MB + st * 16 + 8, (uint32_t)eph);
            EXPTX(MB + st * 16, STGB);
            TMA2D(sb + st * STGB,         &tmA, (ch + NSTG) * 32, bm, MB + st * 16);
            TMA2D(sb + st * STGB + 16384, &tmB, (ch + NSTG) * 32, bn, MB + st * 16);
        }
        if (++st == NSTG) { st = 0; fph ^= 1; eph ^= 1; }
    }

    #pragma unroll
    for (int mt = 0; mt < 2; mt++) {
        #pragma unroll
        for (int nt = 0; nt < 8; nt++) {
            int row = bm + wm * 32 + mt * 16 + g;
            int col = colOff + bn + wn * 64 + nt * 8 + 2 * t4;
            float v[4];
            #pragma unroll
            for (int p = 0; p < 4; p++) {
                float xv = acc[mt][nt][p];
                if (EPI == 3) {
                    if (col < 4096) { float rr = fmaxf(xv, 0.f); xv = rr * rr; }
                    else xv = 1.f / (1.f + __expf(-xv));
                }
                v[p] = xv;
            }
            *(float2*)&Cout[(size_t)row * ldC + col] = make_float2(v[0], v[1]);
            *(float2*)&Cout[(size_t)(row + 8) * ldC + col] = make_float2(v[2], v[3]);
        }
    }
}

// ---------------- rmsnorm (writes tf32-rounded, pslot) ----------------
__global__ void k_rmsnorm(const float* __restrict__ x, float* __restrict__ y) {
    int t = blockIdx.x;
    __shared__ float sx[C];
    __shared__ float red[8];
    const float* xr = x + (size_t)t * C;
    float ss = 0.f;
    for (int i = threadIdx.x; i < C; i += 256) { float v = xr[i]; sx[i] = v; ss += v * v; }
    #pragma unroll
    for (int o = 16; o; o >>= 1) ss += __shfl_xor_sync(0xffffffffu, ss, o);
    if ((threadIdx.x & 31) == 0) red[threadIdx.x >> 5] = ss;
    __syncthreads();
    if (threadIdx.x < 8) {
        float v = red[threadIdx.x];
        #pragma unroll
        for (int o = 4; o; o >>= 1) v += __shfl_xor_sync(0xffu, v, o);
        if (threadIdx.x == 0) red[0] = v;
    }
    __syncthreads();
    float sc = rsqrtf(red[0] / (float)C + 1e-6f);
    float* yr = y + (size_t)t * C;
    for (int i = threadIdx.x; i < C; i += 256) yr[pslot(i)] = tf32r(sx[i] * sc);
}

// ---------------- gate + rope + per-head rmsnorm ----------------
__global__ void k_ropegate(float* __restrict__ QKV, const float* __restrict__ XN,
                           const float* __restrict__ ve, const float* __restrict__ cosb,
                           const float* __restrict__ sinb, const float* __restrict__ wveg) {
    int t = blockIdx.x;
    int tt = t & (T - 1);
    __shared__ float sq[NH * HD];
    __shared__ float sr[NH * HD];
    __shared__ float gsm[NKV];
    int tid = threadIdx.x;
    float* Qb = QKV + (size_t)t * QKVW;
    float* Kb = Qb + 1024;
    float* Vb = Qb + 1280;
    if (tid < NKV) {
        float s = 0.f;
        #pragma unroll
        for (int j = 0; j < VECH; j++)
            s += XN[(size_t)t * C + ((j & 3) << 3) + (j >> 2)] * wveg[tid * VECH + j];
        gsm[tid] = 3.f / (1.f + __expf(-s));
    }
    for (int i = tid; i < NH * HD; i += 256) sq[i] = Qb[i];
    __syncthreads();
    for (int i = tid; i < NH * HD; i += 256) {
        int hh = i >> 6, d = i & 63;
        float val;
        if (d < 32) {
            float cv = cosb[tt * 32 + d], sv = sinb[tt * 32 + d];
            val = sq[hh * 64 + d] * cv + sq[hh * 64 + d + 32] * sv;
        } else {
            int d2 = d - 32;
            float cv = cosb[tt * 32 + d2], sv = sinb[tt * 32 + d2];
            val = -sq[hh * 64 + d2] * sv + sq[hh * 64 + d] * cv;
        }
        sr[i] = val;
    }
    __syncthreads();
    int w = tid >> 5, lane = tid & 31;
    for (int hh = w; hh < NH; hh += 8) {
        float v0 = sr[hh * 64 + lane], v1 = sr[hh * 64 + 32 + lane];
        float ss = v0 * v0 + v1 * v1;
        #pragma unroll
        for (int o = 16; o; o >>= 1) ss += __shfl_xor_sync(0xffffffffu, ss, o);
        float sc = rsqrtf(ss / 64.f + 1e-6f) * 1.2f;
        Qb[hh * 64 + lane] = v0 * sc;
        Qb[hh * 64 + 32 + lane] = v1 * sc;
    }
    __syncthreads();
    for (int i = tid; i < NKV * HD; i += 256) sq[i] = Kb[i];
    __syncthreads();
    for (int i = tid; i < NKV * HD; i += 256) {
        int hh = i >> 6, d = i & 63;
        float val;
        if (d < 32) {
            float cv = cosb[tt * 32 + d], sv = sinb[tt * 32 + d];
            val = sq[hh * 64 + d] * cv + sq[hh * 64 + d + 32] * sv;
        } else {
            int d2 = d - 32;
            float cv = cosb[tt * 32 + d2], sv = sinb[tt * 32 + d2];
            val = -sq[hh * 64 + d2] * sv + sq[hh * 64 + d] * cv;
        }
        sr[i] = val;
    }
    __syncthreads();
    if (w < NKV) {
        int hh = w;
        float v0 = sr[hh * 64 + lane], v1 = sr[hh * 64 + 32 + lane];
        float ss = v0 * v0 + v1 * v1;
        #pragma unroll
        for (int o = 16; o; o >>= 1) ss += __shfl_xor_sync(0xffffffffu, ss, o);
        float sc = rsqrtf(ss / 64.f + 1e-6f) * 1.2f;
        Kb[hh * 64 + lane] = v0 * sc;
        Kb[hh * 64 + 32 + lane] = v1 * sc;
    }
    {
        Vb[tid] = Vb[tid] + gsm[tid >> 6] * ve[(size_t)t * (NKV * HD) + tid];
    }
}

// ---------------- flash attention (Y written pslot) ----------------
__global__ void __launch_bounds__(256) k_flash(const float* __restrict__ QKV, const float* __restrict__ prev,
                        const float* __restrict__ rw, const float* __restrict__ alphap,
                        float* __restrict__ Y) {
    extern __shared__ float smf[];
    float* Qs = smf;
    float* KS = Qs + 64 * 68;
    float* Vt = KS + 64 * 68;
    float* Ps = Vt + 64 * 68;
    float* mrow = Ps + 66 * 66;
    float* lrow = mrow + 64;
    float* crow = lrow + 64;
    int tid = threadIdx.x, lane = tid & 31, w = tid >> 5;
    int g = lane >> 2, t4 = lane & 3;
    int wm = w >> 1, wn = w & 1;
    int qt = gridDim.x - 1 - blockIdx.x;
    int h = blockIdx.y, b = blockIdx.z;
    int q0 = qt * 64, hk = h >> 2;
    float alpha = alphap[0];
    float w9[9];
    #pragma unroll
    for (int i = 0; i < 9; i++) w9[i] = rw[h * 9 + i];

    for (int i = tid; i < 1024; i += 256) {
        int rr = i >> 4, d4 = (i & 15) << 2;
        float4 qv = *(const float4*)&QKV[((size_t)(b * T) + q0 + rr) * QKVW + h * 64 + d4];
        Qs[rr * 68 + pslot(d4 + 0)] = qv.x;
        Qs[rr * 68 + pslot(d4 + 1)] = qv.y;
        Qs[rr * 68 + pslot(d4 + 2)] = qv.z;
        Qs[rr * 68 + pslot(d4 + 3)] = qv.w;
    }
    if (tid < 64) { mrow[tid] = -INFINITY; lrow[tid] = 0.f; }
    float o[4][4];
    #pragma unroll
    for (int i = 0; i < 4; i++)
        #pragma unroll
        for (int j = 0; j < 4; j++) o[i][j] = 0.f;

    for (int kt = 0; kt <= qt; kt++) {
        int k0 = kt * 64;
        __syncthreads();
        for (int i = tid; i < 1024; i += 256) {
            int rr = i >> 4, d4 = (i & 15) << 2;
            const float* basep = &QKV[((size_t)(b * T) + k0 + rr) * QKVW];
            float4 kv = *(const float4*)&basep[1024 + hk * 64 + d4];
            KS[rr * 68 + pslot(d4 + 0)] = kv.x;
            KS[rr * 68 + pslot(d4 + 1)] = kv.y;
            KS[rr * 68 + pslot(d4 + 2)] = kv.z;
            KS[rr * 68 + pslot(d4 + 3)] = kv.w;
            float4 vv = *(const float4*)&basep[1280 + hk * 64 + d4];
            int pr = pslot(rr);
            Vt[(d4 + 0) * 68 + pr] = vv.x;
            Vt[(d4 + 1) * 68 + pr] = vv.y;
            Vt[(d4 + 2) * 68 + pr] = vv.z;
            Vt[(d4 + 3) * 68 + pr] = vv.w;
        }
        for (int idx = tid; idx < 66 * 66; idx += 256) {
            int li = idx / 66, lj = idx - li * 66;
            int gi = q0 - 1 + li, gj = k0 - 1 + lj;
            float v = 0.f;
            if (gi >= 0 && gi < T && gj >= 0 && gj < T)
                v = prev[(((size_t)(b * NH) + h) * T + gi) * T + gj];
            Ps[idx] = v;
        }
        __syncthreads();
        float sacc[4][4];
        #pragma unroll
        for (int i = 0; i < 4; i++)
            #pragma unroll
            for (int j = 0; j < 4; j++) sacc[i][j] = 0.f;
        #pragma unroll
        for (int kp = 0; kp < 4; kp++) {
            int koff = (kp >> 1) * 32 + t4 * 8 + (kp & 1) * 4;
            float4 af0 = *(float4*)&Qs[(wm * 16 + g) * 68 + koff];
            float4 af1 = *(float4*)&Qs[(wm * 16 + 8 + g) * 68 + koff];
            float4 bf[4];
            #pragma unroll
            for (int nt = 0; nt < 4; nt++)
                bf[nt] = *(float4*)&KS[(wn * 32 + nt * 8 + g) * 68 + koff];
            #pragma unroll
            for (int kk = 0; kk < 2; kk++) {
                unsigned a0 = fbits(kk ? af0.z : af0.x), a2 = fbits(kk ? af0.w : af0.y);
                unsigned a1 = fbits(kk ? af1.z : af1.x), a3 = fbits(kk ? af1.w : af1.y);
                #pragma unroll
                for (int nt = 0; nt < 4; nt++) {
                    unsigned b0 = fbits(kk ? bf[nt].z : bf[nt].x);
                    unsigned b1 = fbits(kk ? bf[nt].w : bf[nt].y);
                    mma8(sacc[nt], a0, a1, a2, a3, b0, b1);
                }
            }
        }
        __syncthreads();
        #pragma unroll
        for (int nt = 0; nt < 4; nt++) {
            #pragma unroll
            for (int rg = 0; rg < 2; rg++) {
                int ri = wm * 16 + g + rg * 8;
                int cj = wn * 32 + nt * 8 + 2 * t4;
                float p[3][4];
                #pragma unroll
                for (int a = 0; a < 3; a++) {
                    float2 x0 = *(float2*)&Ps[(ri + a) * 66 + cj];
                    float2 x1 = *(float2*)&Ps[(ri + a) * 66 + cj + 2];
                    p[a][0] = x0.x; p[a][1] = x0.y; p[a][2] = x1.x; p[a][3] = x1.y;
                }
                float cv0 = 0.f, cv1 = 0.f;
                #pragma unroll
                for (int a = 0; a < 3; a++)
                    #pragma unroll
                    for (int bb = 0; bb < 3; bb++) {
                        cv0 = fmaf(w9[a * 3 + bb], p[a][bb], cv0);
                        cv1 = fmaf(w9[a * 3 + bb], p[a][bb + 1], cv1);
                    }
                float v0 = sacc[nt][rg * 2 + 0] * 0.125f + alpha * cv0;
                float v1 = sacc[nt][rg * 2 + 1] * 0.125f + alpha * cv1;
                if (k0 + cj > q0 + ri) v0 = -INFINITY;
                if (k0 + cj + 1 > q0 + ri) v1 = -INFINITY;
                KS[ri * 68 + pslot(cj)] = v0;
                KS[ri * 68 + pslot(cj + 1)] = v1;
            }
        }
        __syncthreads();
        {
            int row = tid >> 2, part = tid & 3;
            float* srow = KS + row * 68 + part * 16;
            float4 s0 = *(float4*)&srow[0], s1 = *(float4*)&srow[4];
            float4 s2 = *(float4*)&srow[8], s3 = *(float4*)&srow[12];
            float rm = fmaxf(fmaxf(fmaxf(s0.x, s0.y), fmaxf(s0.z, s0.w)),
                             fmaxf(fmaxf(s1.x, s1.y), fmaxf(s1.z, s1.w)));
            rm = fmaxf(rm, fmaxf(fmaxf(fmaxf(s2.x, s2.y), fmaxf(s2.z, s2.w)),
                                 fmaxf(fmaxf(s3.x, s3.y), fmaxf(s3.z, s3.w))));
            rm = fmaxf(rm, __shfl_xor_sync(0xffffffffu, rm, 1));
            rm = fmaxf(rm, __shfl_xor_sync(0xffffffffu, rm, 2));
            float mo = mrow[row];
            float nm = fmaxf(mo, rm);
            float sum = 0.f;
            #define EXA(v) v.x = __expf(v.x - nm); v.y = __expf(v.y - nm); \
                           v.z = __expf(v.z - nm); v.w = __expf(v.w - nm); \
                           sum += v.x + v.y + v.z + v.w;
            EXA(s0) EXA(s1) EXA(s2) EXA(s3)
            #undef EXA
            *(float4*)&srow[0] = s0; *(float4*)&srow[4] = s1;
            *(float4*)&srow[8] = s2; *(float4*)&srow[12] = s3;
            sum += __shfl_xor_sync(0xffffffffu, sum, 1);
            sum += __shfl_xor_sync(0xffffffffu, sum, 2);
            if (part == 0) {
                float corr = __expf(mo - nm);
                mrow[row] = nm;
                lrow[row] = lrow[row] * corr + sum;
                crow[row] = corr;
            }
        }
        __syncthreads();
        float c0 = crow[wm * 16 + g], c1 = crow[wm * 16 + 8 + g];
        #pragma unroll
        for (int nt = 0; nt < 4; nt++) {
            o[nt][0] *= c0; o[nt][1] *= c0; o[nt][2] *= c1; o[nt][3] *= c1;
        }
        #pragma unroll
        for (int kp = 0; kp < 4; kp++) {
            int koff = (kp >> 1) * 32 + t4 * 8 + (kp & 1) * 4;
            float4 af0 = *(float4*)&KS[(wm * 16 + g) * 68 + koff];
            float4 af1 = *(float4*)&KS[(wm * 16 + 8 + g) * 68 + koff];
            float4 bf[4];
            #pragma unroll
            for (int nt = 0; nt < 4; nt++)
                bf[nt] = *(float4*)&Vt[(wn * 32 + nt * 8 + g) * 68 + koff];
            #pragma unroll
            for (int kk = 0; kk < 2; kk++) {
                unsigned a0 = fbits(kk ? af0.z : af0.x), a2 = fbits(kk ? af0.w : af0.y);
                unsigned a1 = fbits(kk ? af1.z : af1.x), a3 = fbits(kk ? af1.w : af1.y);
                #pragma unroll
                for (int nt = 0; nt < 4; nt++) {
                    unsigned b0 = fbits(kk ? bf[nt].z : bf[nt].x);
                    unsigned b1 = fbits(kk ? bf[nt].w : bf[nt].y);
                    mma8(o[nt], a0, a1, a2, a3, b0, b1);
                }
            }
        }
    }
    {
        float inv0 = 1.f / lrow[wm * 16 + g];
        float inv1 = 1.f / lrow[wm * 16 + 8 + g];
        int r0 = q0 + wm * 16 + g;
        #pragma unroll
        for (int nt = 0; nt < 4; nt++) {
            int cj = wn * 32 + nt * 8 + 2 * t4;
            int c0i = h * 64 + cj;
            Y[((size_t)(b * T) + r0) * C + pslot(c0i)] = o[nt][0] * inv0;
            Y[((size_t)(b * T) + r0) * C + pslot(c0i + 1)] = o[nt][1] * inv0;
            Y[((size_t)(b * T) + r0 + 8) * C + pslot(c0i)] = o[nt][2] * inv1;
            Y[((size_t)(b * T) + r0 + 8) * C + pslot(c0i + 1)] = o[nt][3] * inv1;
        }
    }
}

// ---------------- small kernels ----------------
__global__ void k_dot32(const float* __restrict__ X, const float* __restrict__ W,
                        float* __restrict__ OUT) {
    __shared__ float sx[8 * C];
    int t0 = blockIdx.x * 8;
    for (int i = threadIdx.x; i < 8 * C; i += 256) sx[i] = X[(size_t)t0 * C + i];
    __syncthreads();
    int tok = threadIdx.x >> 5, oo = threadIdx.x & 31;
    const float4* wr = (const float4*)(W + (size_t)oo * C);
    const float4* xr = (const float4*)(sx + tok * C);
    float s = 0.f;
    #pragma unroll 4
    for (int k = 0; k < C / 4; k++) {
        float4 a = xr[k], b = wr[k];
        s += a.x * b.x + a.y * b.y + a.z * b.z + a.w * b.w;
    }
    OUT[(size_t)(t0 + tok) * CADIM + oo] = s;
}

__global__ void k_caconv(const float* __restrict__ R, const float* __restrict__ cw,
                         float* __restrict__ OUT) {
    int b = blockIdx.y, t0 = blockIdx.x * 128;
    __shared__ float s[130 * 32];
    __shared__ float w[32 * 3];
    for (int i = threadIdx.x; i < 96; i += 256) w[i] = cw[i];
    for (int i = threadIdx.x; i < 130 * 32; i += 256) {
        int r = i >> 5, c = i & 31;
        int t = t0 - 1 + r;
        s[i] = (t >= 0 && t < T) ? R[((size_t)(b * T) + t) * CADIM + c] : 0.f;
    }
    __syncthreads();
    for (int i = threadIdx.x; i < 128 * 32; i += 256) {
        int r = i >> 5, c = i & 31;
        float h0 = s[(r + 1) * 32 + c];
        float cv = w[c * 3 + 0] * s[r * 32 + c] + w[c * 3 + 1] * h0 + w[c * 3 + 2] * s[(r + 2) * 32 + c];
        float v = h0 + 0.1f * cv;
        v = 0.5f * v * (1.f + erff(v * 0.70710678118f));
        OUT[((size_t)(b * T) + t0 + r) * CADIM + c] = v;
    }
}

__global__ void k_x1(const float* __restrict__ x, const float* __restrict__ attn,
                     const float* __restrict__ cah, const float* __restrict__ capo,
                     float* __restrict__ X1) {
    int tg = blockIdx.x;
    __shared__ float h[16 * 32];
    __shared__ float po[256 * 33];
    int tid = threadIdx.x;
    for (int i = tid; i < 16 * 32; i += 256) h[i] = cah[(size_t)tg * 16 * 32 + i];
    for (int cc = 0; cc < 4; cc++) {
        int c0 = cc * 256;
        __syncthreads();
        for (int i = tid; i < 256 * 32; i += 256) po[(i >> 5) * 33 + (i & 31)] = capo[(size_t)c0 * 32 + i];
        __syncthreads();
        float wv[32];
        #pragma unroll
        for (int j = 0; j < 32; j++) wv[j] = po[tid * 33 + j];
        int c = c0 + tid;
        for (int tok = 0; tok < 16; tok++) {
            float ca = 0.f;
            #pragma unroll
            for (int j = 0; j < 32; j++) ca = fmaf(wv[j], h[tok * 32 + j], ca);
            size_t idx = ((size_t)tg * 16 + tok) * C + c;
            X1[idx] = x[idx] + attn[idx] * (1.f + 0.1f * tanhf(ca));
        }
    }
}

__global__ void k_ffnconv(const float* __restrict__ Hin, const float* __restrict__ cw,
                          float* __restrict__ Hout) {
    int c0 = blockIdx.x * 32, t0 = blockIdx.y * 64, b = blockIdx.z;
    __shared__ float bufA[72 * 32];
    __shared__ float bufB[72 * 32];
    __shared__ float w[32 * 3];
    int tid = threadIdx.x;
    for (int i = tid; i < 96; i += 256) w[i] = cw[(size_t)c0 * 3 + i];
    for (int i = tid; i < 72 * 32; i += 256) {
        int r = i >> 5, c = i & 31;
        int t = t0 - 4 + r;
        bufA[i] = (t >= 0 && t < T) ? Hin[((size_t)(b * T) + t) * FW + c0 + c] : 0.f;
    }
    float* A = bufA;
    float* Bf = bufB;
    for (int it = 0; it < 4; it++) {
        __syncthreads();
        for (int i = tid; i < 72 * 32; i += 256) {
            int r = i >> 5, c = i & 31;
            int t = t0 - 4 + r;
            float v = 0.f;
            if (t >= 0 && t < T) {
                float am = (r > 0) ? A[(r - 1) * 32 + c] : 0.f;
                float a0 = A[i];
                float ap = (r < 71) ? A[(r + 1) * 32 + c] : 0.f;
                v = a0 + 0.1f * (w[c * 3] * am + w[c * 3 + 1] * a0 + w[c * 3 + 2] * ap);
            }
            Bf[i] = v;
        }
        float* tmp = A; A = Bf; Bf = tmp;
    }
    __syncthreads();
    for (int i = tid; i < 64 * 32; i += 256) {
        int r = i >> 5, c = i & 31;
        int s = c0 + ((c & 3) << 3) + (c >> 2);
        Hout[((size_t)(b * T) + t0 + r) * FFNH + s] = tf32r(A[(r + 4) * 32 + c]);
    }
}

__global__ void k_vitpost(const float* __restrict__ VR, const float* __restrict__ w2,
                          float* __restrict__ VIT) {
    int t = blockIdx.x * 256 + threadIdx.x;
    float s = 0.f;
    #pragma unroll
    for (int j = 0; j < 32; j++) {
        float v = VR[(size_t)t * 32 + j];
        v = 0.5f * v * (1.f + erff(v * 0.70710678118f));
        s += v * w2[j];
    }
    VIT[t] = 1.f / (1.f + __expf(-s));
}

__global__ void k_vsmooth(const float* __restrict__ VIT, float* __restrict__ VITF) {
    int b = blockIdx.x;
    for (int t = threadIdx.x; t < T; t += 256) {
        float v = VIT[b * T + t];
        float s = 0.f;
        #pragma unroll
        for (int d = -2; d <= 2; d++) {
            int tt = t + d;
            if (tt >= 0 && tt < T) s += VIT[b * T + tt];
        }
        s *= 0.2f;
        float f = 0.7f * v + 0.3f * s;
        VITF[b * T + t] = (f > 0.3f) ? f : 0.1f * f;
    }
}

__global__ void k_final(const float* __restrict__ x1, const float* __restrict__ mlp,
                        const float* __restrict__ HG, const float* __restrict__ cah,
                        const float* __restrict__ capo, const float* __restrict__ vitf,
                        float* __restrict__ out) {
    int tg = blockIdx.x;
    __shared__ float h[16 * 32];
    __shared__ float po[256 * 33];
    __shared__ float sv[16];
    int tid = threadIdx.x;
    for (int i = tid; i < 16 * 32; i += 256) h[i] = cah[(size_t)tg * 16 * 32 + i];
    if (tid < 16) sv[tid] = vitf[tg * 16 + tid];
    for (int cc = 0; cc < 4; cc++) {
        int c0 = cc * 256;
        __syncthreads();
        for (int i = tid; i < 256 * 32; i += 256) po[(i >> 5) * 33 + (i & 31)] = capo[(size_t)c0 * 32 + i];
        __syncthreads();
        float wv[32];
        #pragma unroll
        for (int j = 0; j < 32; j++) wv[j] = po[tid * 33 + j];
        int c = c0 + tid;
        for (int tok = 0; tok < 16; tok++) {
            float ca = 0.f;
            #pragma unroll
            for (int j = 0; j < 32; j++) ca = fmaf(wv[j], h[tok * 32 + j], ca);
            size_t idx = ((size_t)tg * 16 + tok) * C + c;
            float gate = HG[((size_t)tg * 16 + tok) * FW + 4096 + c];
            float m = mlp[idx] * gate * (1.f + 0.1f * tanhf(ca)) * sv[tok];
            out[idx] = x1[idx] + m;
        }
    }
}

// ---------------- host ----------------
typedef CUresult (*PFN_tmenc)(CUtensorMap*, CUtensorMapDataType, cuuint32_t, void*,
                              const cuuint64_t*, const cuuint64_t*, const cuuint32_t*,
                              const cuuint32_t*, CUtensorMapInterleave, CUtensorMapSwizzle,
                              CUtensorMapL2promotion, CUtensorMapFloatOOBfill);
static PFN_tmenc tmenc() {
    static PFN_tmenc fp = nullptr;
    if (!fp) {
        void* p = nullptr;
        cudaDriverEntryPointQueryResult qr;
        cudaGetDriverEntryPoint("cuTensorMapEncodeTiled", &p, cudaEnableDefault, &qr);
        fp = (PFN_tmenc)p;
    }
    return fp;
}
static void mk_tmap(CUtensorMap* m, const void* ptr, int M, int K) {
    cuuint64_t dims[2] = {(cuuint64_t)K, (cuuint64_t)M};
    cuuint64_t strides[1] = {(cuuint64_t)K * 4};
    cuuint32_t box[2] = {32, 128};
    cuuint32_t es[2] = {1, 1};
    tmenc()(m, CU_TENSOR_MAP_DATA_TYPE_FLOAT32, 2, (void*)ptr, dims, strides, box, es,
            CU_TENSOR_MAP_INTERLEAVE_NONE, CU_TENSOR_MAP_SWIZZLE_128B,
            CU_TENSOR_MAP_L2_PROMOTION_L2_128B, CU_TENSOR_MAP_FLOAT_OOB_FILL_NONE);
}

extern "C" void kernel_launch(void* const* d_in, const int* in_sizes, int n_in,
                              void* d_out, int out_size) {
    const float* x        = (const float*)d_in[0];
    const float* ve       = (const float*)d_in[1];
    const float* cosb     = (const float*)d_in[2];
    const float* sinb     = (const float*)d_in[3];
    const float* prev     = (const float*)d_in[4];
    const float* w_q      = (const float*)d_in[5];
    const float* w_k      = (const float*)d_in[6];
    const float* w_v      = (const float*)d_in[7];
    const float* w_o      = (const float*)d_in[8];
    const float* w_veg    = (const float*)d_in[9];
    const float* refine_w = (const float*)d_in[10];
    const float* alpha    = (const float*)d_in[11];
    const float* ca_pi    = (const float*)d_in[12];
    const float* ca_cw    = (const float*)d_in[13];
    const float* ca_po    = (const float*)d_in[14];
    const float* ffn_in   = (const float*)d_in[15];
    const float* ffn_cw   = (const float*)d_in[16];
    const float* ffn_out  = (const float*)d_in[17];
    const float* ffn_gate = (const float*)d_in[18];
    const float* vit_w1   = (const float*)d_in[19];
    const float* vit_w2   = (const float*)d_in[20];
    float* out = (float*)d_out;

    float *XN, *QKV, *Yp, *ATT, *X1, *XM, *HG, *H2, *MLP, *CR1, *CA1, *CR2, *CA2, *VR, *VIT, *VITF;
    float *WQKVp, *WOp, *WFp, *WFOp;
    cudaGetSymbolAddress((void**)&XN, g_XN);
    cudaGetSymbolAddress((void**)&QKV, g_QKV);
    cudaGetSymbolAddress((void**)&Yp, g_Y);
    cudaGetSymbolAddress((void**)&ATT, g_ATT);
    cudaGetSymbolAddress((void**)&X1, g_X1);
    cudaGetSymbolAddress((void**)&XM, g_XM);
    cudaGetSymbolAddress((void**)&HG, g_HG);
    cudaGetSymbolAddress((void**)&H2, g_H2);
    cudaGetSymbolAddress((void**)&MLP, g_MLP);
    cudaGetSymbolAddress((void**)&CR1, g_CR1);
    cudaGetSymbolAddress((void**)&CA1, g_CA1);
    cudaGetSymbolAddress((void**)&CR2, g_CR2);
    cudaGetSymbolAddress((void**)&CA2, g_CA2);
    cudaGetSymbolAddress((void**)&VR, g_VR);
    cudaGetSymbolAddress((void**)&VIT, g_VIT);
    cudaGetSymbolAddress((void**)&VITF, g_VITF);
    cudaGetSymbolAddress((void**)&WQKVp, g_WQKVp);
    cudaGetSymbolAddress((void**)&WOp, g_WOp);
    cudaGetSymbolAddress((void**)&WFp, g_WFp);
    cudaGetSymbolAddress((void**)&WFOp, g_WFOp);

    static CUtensorMap tXN, tWQKV, tY, tWO, tXM, tWF, tH2, tWFO;
    mk_tmap(&tXN, XN, BT, C);
    mk_tmap(&tWQKV, WQKVp, QKVW, C);
    mk_tmap(&tY, Yp, BT, C);
    mk_tmap(&tWO, WOp, 1024, C);
    mk_tmap(&tXM, XM, BT, C);
    mk_tmap(&tWF, WFp, FW, C);
    mk_tmap(&tH2, H2, BT, FFNH);
    mk_tmap(&tWFO, WFOp, 1024, FFNH);

    cudaFuncSetAttribute(k_tgemm<0>, cudaFuncAttributeMaxDynamicSharedMemorySize, TG_SMEM);
    cudaFuncSetAttribute(k_tgemm<3>, cudaFuncAttributeMaxDynamicSharedMemorySize, TG_SMEM);
    const int smemf = (3 * 64 * 68 + 66 * 66 + 3 * 64) * (int)sizeof(float);
    cudaFuncSetAttribute(k_flash, cudaFuncAttributeMaxDynamicSharedMemorySize, smemf);

    static cudaStream_t sA = nullptr, sB = nullptr;
    static cudaEvent_t eF, eWqkv, eWrest, eCA1, eX1, eS2, eEnd;
    if (!sA) {
        cudaStreamCreateWithFlags(&sA, cudaStreamNonBlocking);
        cudaStreamCreateWithFlags(&sB, cudaStreamNonBlocking);
        cudaEventCreateWithFlags(&eF, cudaEventDisableTiming);
        cudaEventCreateWithFlags(&eWqkv, cudaEventDisableTiming);
        cudaEventCreateWithFlags(&eWrest, cudaEventDisableTiming);
        cudaEventCreateWithFlags(&eCA1, cudaEventDisableTiming);
        cudaEventCreateWithFlags(&eX1, cudaEventDisableTiming);
        cudaEventCreateWithFlags(&eS2, cudaEventDisableTiming);
        cudaEventCreateWithFlags(&eEnd, cudaEventDisableTiming);
    }

    cudaEventRecord(eF, 0);
    cudaStreamWaitEvent(sA, eF, 0);
    cudaStreamWaitEvent(sB, eF, 0);

    k_rmsnorm<<<BT, 256, 0, sA>>>(x, XN);
    k_permw4<<<(1024 * 256 + 255) / 256, 256, 0, sB>>>(w_q, WQKVp, 1024 * 256, 1023);
    k_permw4<<<(256 * 256 + 255) / 256, 256, 0, sB>>>(w_k, WQKVp + 1024 * C, 256 * 256, 1023);
    k_permw4<<<(256 * 256 + 255) / 256, 256, 0, sB>>>(w_v, WQKVp + 1280 * C, 256 * 256, 1023);
    cudaEventRecord(eWqkv, sB);
    k_dot32<<<BT / 8, 256, 0, sB>>>(x, ca_pi, CR1);
    cudaStreamWaitEvent(sA, eWqkv, 0);
    k_tgemm<0><<<dim3(QKVW / 128, 32), 256, TG_SMEM, sA>>>(tXN, tWQKV, QKV, QKVW, 0, C);
    k_caconv<<<dim3(T / 128, BB), 256, 0, sB>>>(CR1, ca_cw, CA1);
    cudaEventRecord(eCA1, sB);
    k_permw4<<<(1024 * 256 + 255) / 256, 256, 0, sB>>>(w_o, WOp, 1024 * 256, 1023);
    k_permw4<<<(4096 * 256 + 255) / 256, 256, 0, sB>>>(ffn_in, WFp, 4096 * 256, 1023);
    k_permw4<<<(1024 * 256 + 255) / 256, 256, 0, sB>>>(ffn_gate, WFp + (size_t)4096 * C, 1024 * 256, 1023);
    k_permw4<<<(1024 * 1024 + 255) / 256, 256, 0, sB>>>(ffn_out, WFOp, 1024 * 1024, 4095);
    cudaEventRecord(eWrest, sB);

    k_ropegate<<<BT, 256, 0, sA>>>(QKV, XN, ve, cosb, sinb, w_veg);
    k_flash<<<dim3(T / 64, NH, BB), 256, smemf, sA>>>(QKV, prev, refine_w, alpha, Yp);
    cudaStreamWaitEvent(sA, eWrest, 0);
    k_tgemm<0><<<dim3(8, 32), 256, TG_SMEM, sA>>>(tY, tWO, ATT, C, 0, C);
    cudaStreamWaitEvent(sA, eCA1, 0);
    k_x1<<<BT / 16, 256, 0, sA>>>(x, ATT, CA1, ca_po, X1);
    cudaEventRecord(eX1, sA);

    k_rmsnorm<<<BT, 256, 0, sA>>>(X1, XM);
    k_tgemm<3><<<dim3(FW / 128, 32), 256, TG_SMEM, sA>>>(tXM, tWF, HG, FW, 0, C);
    cudaStreamWaitEvent(sB, eX1, 0);
    k_dot32<<<BT / 8, 256, 0, sB>>>(X1, ca_pi, CR2);
    k_caconv<<<dim3(T / 128, BB), 256, 0, sB>>>(CR2, ca_cw, CA2);
    k_dot32<<<BT / 8, 256, 0, sB>>>(X1, vit_w1, VR);
    k_vitpost<<<BT / 256, 256, 0, sB>>>(VR, vit_w2, VIT);
    k_vsmooth<<<BB, 256, 0, sB>>>(VIT, VITF);
    cudaEventRecord(eS2, sB);

    k_ffnconv<<<dim3(FFNH / 32, T / 64, BB), 256, 0, sA>>>(HG, ffn_cw, H2);
    k_tgemm<0><<<dim3(8, 32), 256, TG_SMEM, sA>>>(tH2, tWFO, MLP, C, 0, FFNH);
    cudaStreamWaitEvent(sA, eS2, 0);
    k_final<<<BT / 16, 256, 0, sA>>>(X1, MLP, HG, CA2, ca_po, VITF, out);

    cudaEventRecord(eEnd, sA);
    cudaStreamWaitEvent(0, eEnd, 0);
}